// round 10
// baseline (speedup 1.0000x reference)
#include <cuda_runtime.h>
#include <cuda_bf16.h>
#include <cstdint>
#include <math.h>

#define NN 50000
#define NE 800000

// ---------------- scratch (static device globals; no allocation) ----------------
__device__ int   g_is64;
__device__ int   g_deg[NN];
__device__ int   g_off[NN + 1];
__device__ int   g_cur[NN];
__device__ int   g_csr[NE];
__device__ int   g_bsum[64];
__device__ float g_amp[NN];
__device__ float g_att[NN];
__device__ float g_P[NN * 128];
__device__ float g_Q[NN * 128];
__device__ float g_agg[NN * 384];
// current h as bf16 hi/lo images (the ONLY representation between layers)
__device__ unsigned short g_hbh[NN * 128];
__device__ unsigned short g_hbl[NN * 128];
// prepacked weights, PER LAYER: PQ [256 rows (P|Q)][128 K], update [N][1280 K]
__device__ unsigned short g_PQhi[3][256 * 128];
__device__ unsigned short g_PQlo[3][256 * 128];
__device__ unsigned short g_Uhi[3][128 * 1280];
__device__ unsigned short g_Ulo[3][128 * 1280];

// ---------------- helpers ----------------
__device__ __forceinline__ uint32_t smem_u32(const void* p) {
    uint32_t a;
    asm("{ .reg .u64 t; cvta.to.shared.u64 t, %1; cvt.u32.u64 %0, t; }"
        : "=r"(a) : "l"(p));
    return a;
}
__device__ __forceinline__ void ldsm4(uint32_t* r, uint32_t addr) {
    asm volatile("ldmatrix.sync.aligned.m8n8.x4.shared.b16 {%0,%1,%2,%3}, [%4];"
                 : "=r"(r[0]), "=r"(r[1]), "=r"(r[2]), "=r"(r[3]) : "r"(addr));
}
__device__ __forceinline__ void mma16816(float* c, const uint32_t* a,
                                         uint32_t b0, uint32_t b1) {
    asm volatile("mma.sync.aligned.m16n8k16.row.col.f32.bf16.bf16.f32 "
                 "{%0,%1,%2,%3}, {%4,%5,%6,%7}, {%8,%9}, {%0,%1,%2,%3};"
                 : "+f"(c[0]), "+f"(c[1]), "+f"(c[2]), "+f"(c[3])
                 : "r"(a[0]), "r"(a[1]), "r"(a[2]), "r"(a[3]), "r"(b0), "r"(b1));
}
__device__ __forceinline__ void cp_async16(uint32_t daddr, const void* gptr) {
    asm volatile("cp.async.cg.shared.global [%0], [%1], 16;"
                 :: "r"(daddr), "l"(gptr));
}
#define CP_COMMIT() asm volatile("cp.async.commit_group;" ::: "memory")
#define CP_WAIT1()  asm volatile("cp.async.wait_group 1;" ::: "memory")
#define CP_WAIT0()  asm volatile("cp.async.wait_group 0;" ::: "memory")

__device__ __forceinline__ uint16_t bfh(float v) {
    return __bfloat16_as_ushort(__float2bfloat16(v));
}
__device__ __forceinline__ uint16_t bfl(float v) {
    __nv_bfloat16 h = __float2bfloat16(v);
    return __bfloat16_as_ushort(__float2bfloat16(v - __bfloat162float(h)));
}

// 16 fp32 -> bf16 hi/lo (scaled), packed as 2+2 uint4
__device__ __forceinline__ void conv16(const float4* f, float s, uint4* Hv, uint4* Lv) {
    uint32_t hw[8], lw[8];
    #pragma unroll
    for (int q = 0; q < 4; q++) {
        float v[4] = {f[q].x * s, f[q].y * s, f[q].z * s, f[q].w * s};
        uint16_t hb[4], lb[4];
        #pragma unroll
        for (int i = 0; i < 4; i++) {
            __nv_bfloat16 h = __float2bfloat16(v[i]);
            float hf        = __bfloat162float(h);
            __nv_bfloat16 l = __float2bfloat16(v[i] - hf);
            hb[i] = __bfloat16_as_ushort(h);
            lb[i] = __bfloat16_as_ushort(l);
        }
        hw[q * 2 + 0] = (uint32_t)hb[0] | ((uint32_t)hb[1] << 16);
        hw[q * 2 + 1] = (uint32_t)hb[2] | ((uint32_t)hb[3] << 16);
        lw[q * 2 + 0] = (uint32_t)lb[0] | ((uint32_t)lb[1] << 16);
        lw[q * 2 + 1] = (uint32_t)lb[2] | ((uint32_t)lb[3] << 16);
    }
    Hv[0] = make_uint4(hw[0], hw[1], hw[2], hw[3]);
    Hv[1] = make_uint4(hw[4], hw[5], hw[6], hw[7]);
    Lv[0] = make_uint4(lw[0], lw[1], lw[2], lw[3]);
    Lv[1] = make_uint4(lw[4], lw[5], lw[6], lw[7]);
}

// ---------------- x -> bf16 hi/lo seed ----------------
__global__ void conv_x(const float* __restrict__ x, int n) {
    int idx = blockIdx.x * blockDim.x + threadIdx.x;
    if (idx * 4 >= n * 128) return;
    float4 v = *(const float4*)(x + (size_t)idx * 4);
    uint32_t h0 = (uint32_t)bfh(v.x) | ((uint32_t)bfh(v.y) << 16);
    uint32_t h1 = (uint32_t)bfh(v.z) | ((uint32_t)bfh(v.w) << 16);
    uint32_t l0 = (uint32_t)bfl(v.x) | ((uint32_t)bfl(v.y) << 16);
    uint32_t l1 = (uint32_t)bfl(v.z) | ((uint32_t)bfl(v.w) << 16);
    *(uint2*)(g_hbh + (size_t)idx * 4) = make_uint2(h0, h1);
    *(uint2*)(g_hbl + (size_t)idx * 4) = make_uint2(l0, l1);
}

// ---------------- index-width detection ----------------
__global__ void detect_kernel(const void* dst, int e, int n) {
    __shared__ int bad;
    if (threadIdx.x == 0) bad = 0;
    __syncthreads();
    int k = e < 1024 ? e : 1024;
    const long long* p = (const long long*)dst;
    for (int i = threadIdx.x; i < k; i += blockDim.x) {
        long long v = p[i];
        if (v < 0 || v >= (long long)n) atomicExch(&bad, 1);
    }
    __syncthreads();
    if (threadIdx.x == 0) g_is64 = bad ? 0 : 1;
}
__device__ __forceinline__ int load_idx(const void* p, int i) {
    if (g_is64) return (int)((const long long*)p)[i];
    return ((const int*)p)[i];
}

// ---------------- CSR build ----------------
__global__ void zero_deg(int n) {
    int i = blockIdx.x * blockDim.x + threadIdx.x;
    if (i < n) g_deg[i] = 0;
}
__global__ void hist_kernel(const void* __restrict__ dst, int e) {
    int i = blockIdx.x * blockDim.x + threadIdx.x;
    if (i < e) atomicAdd(&g_deg[load_idx(dst, i)], 1);
}

__global__ void scan_p1(int n) {
    int base = blockIdx.x * 1024 + threadIdx.x * 4;
    int s = 0;
    #pragma unroll
    for (int j = 0; j < 4; j++) {
        int i = base + j;
        if (i < n) s += g_deg[i];
    }
    #pragma unroll
    for (int o = 16; o; o >>= 1) s += __shfl_down_sync(0xFFFFFFFFu, s, o);
    __shared__ int ws[8];
    if ((threadIdx.x & 31) == 0) ws[threadIdx.x >> 5] = s;
    __syncthreads();
    if (threadIdx.x == 0) {
        int t = 0;
        #pragma unroll
        for (int w = 0; w < 8; w++) t += ws[w];
        g_bsum[blockIdx.x] = t;
    }
}
__global__ void scan_p2(int nb, int n) {
    int tid = threadIdx.x;
    int v = tid < nb ? g_bsum[tid] : 0;
    __shared__ int tmp[64];
    tmp[tid] = v;
    __syncthreads();
    #pragma unroll
    for (int o = 1; o < 64; o <<= 1) {
        int t = tid >= o ? tmp[tid - o] : 0;
        __syncthreads();
        tmp[tid] += t;
        __syncthreads();
    }
    if (tid < nb) g_bsum[tid] = tmp[tid] - v;
    if (tid == 0) g_off[n] = tmp[63];
}
__global__ void scan_p3(int n) {
    int tid  = threadIdx.x;
    int base = blockIdx.x * 1024 + tid * 4;
    int d[4], s = 0;
    #pragma unroll
    for (int j = 0; j < 4; j++) {
        int i = base + j;
        d[j] = (i < n) ? g_deg[i] : 0;
        s += d[j];
    }
    int lane = tid & 31, w = tid >> 5;
    int incl = s;
    #pragma unroll
    for (int o = 1; o < 32; o <<= 1) {
        int t = __shfl_up_sync(0xFFFFFFFFu, incl, o);
        if (lane >= o) incl += t;
    }
    __shared__ int ws[8];
    if (lane == 31) ws[w] = incl;
    __syncthreads();
    if (tid == 0) {
        int acc = 0;
        #pragma unroll
        for (int q = 0; q < 8; q++) { int t = ws[q]; ws[q] = acc; acc += t; }
    }
    __syncthreads();
    int run = incl - s + ws[w] + g_bsum[blockIdx.x];
    #pragma unroll
    for (int j = 0; j < 4; j++) {
        int i = base + j;
        if (i < n) {
            g_off[i] = run;
            g_cur[i] = run;
            float ld = logf((float)d[j] + 1.0f);
            g_amp[i] = ld * (1.0f / 3.0f);
            g_att[i] = 3.0f / fmaxf(ld, 1e-6f);
            run += d[j];
        }
    }
}

__global__ void scatter_kernel(const void* __restrict__ src,
                               const void* __restrict__ dst, int e) {
    int i = blockIdx.x * blockDim.x + threadIdx.x;
    if (i < e) {
        int d   = load_idx(dst, i);
        int pos = atomicAdd(&g_cur[d], 1);
        g_csr[pos] = load_idx(src, i);
    }
}

// ---------------- weight prepack (per-layer buffers) ----------------
template <int L>
__global__ void prepack_upd2(const float* __restrict__ Uw, int N) {
    int idx = blockIdx.x * blockDim.x + threadIdx.x;
    if (idx >= 1280 * N) return;
    int k = idx / N, n = idx % N;
    float v = Uw[idx];
    size_t pos = (size_t)n * 1280 + k;
    g_Uhi[L][pos] = bfh(v);
    g_Ulo[L][pos] = bfl(v);
}
template <int L>
__global__ void prepack_pq2(const float* __restrict__ Mw) {
    int idx = blockIdx.x * blockDim.x + threadIdx.x;
    if (idx >= 256 * 128) return;
    int n = idx >> 7, k = idx & 127;
    int mat = n >> 7, nn = n & 127;
    float v = Mw[(mat * 128 + k) * 128 + nn];
    size_t pos = (size_t)n * 128 + k;
    g_PQhi[L][pos] = bfh(v);
    g_PQlo[L][pos] = bfl(v);
}

// ---------------- mma.sync update GEMM, cp.async B + A-prefetch pipeline ------
// A = [h(bf16 images) | agg | agg*amp | agg*att]; C -> d_out (FINAL) or hb images
template <int FINAL, int BN, bool RELU, int L>
__global__ __launch_bounds__(256, 2) void mma_update(const float* __restrict__ Ub,
                                                     float* __restrict__ outp, int M) {
    constexpr int KTOT = 1280, NCH = 40, WNT = BN / 16;
    constexpr int SB_STAGE = 2 * BN * 40;
    extern __shared__ __align__(16) char dyn[];
    uint16_t* sA = (uint16_t*)dyn;            // [2][128][40]
    uint16_t* sB = (uint16_t*)(dyn + 20480);  // [2 stages][2 imgs][BN][40]

    int tid = threadIdx.x, lane = tid & 31, wid = tid >> 5;
    int wm = wid & 3, wn = wid >> 2;
    int row0  = blockIdx.x * 128;
    int arow  = tid >> 1, ahalf = (tid & 1) * 16;
    int gr_a  = row0 + arow;
    bool va   = gr_a < M;
    float s_amp = va ? g_amp[gr_a] : 0.f;
    float s_att = va ? g_att[gr_a] : 0.f;

    float acc[2][WNT][4];
    #pragma unroll
    for (int mt = 0; mt < 2; mt++)
        #pragma unroll
        for (int t = 0; t < WNT; t++)
            #pragma unroll
            for (int j = 0; j < 4; j++) acc[mt][t][j] = 0.f;

    uint32_t a_base = smem_u32(sA);
    uint32_t b_base = smem_u32(sB);
    int lrow = lane & 15, lcol = (lane >> 4) * 8;

    auto ascale = [&](int k0) -> float {
        if (k0 < 512) return 1.f;
        else if (k0 < 896) return s_amp;
        else return s_att;
    };
    // prefetch A fragment for chunk c into p[4] (h chunks: bf16 images; agg: fp32)
    auto prefA = [&](int c, uint4* p) {
        uint4 z = make_uint4(0, 0, 0, 0);
        if (c < 4) {  // k0 < 128: h from bf16 images
            const uint4* hh = (const uint4*)(g_hbh + (size_t)gr_a * 128 + c * 32 + ahalf);
            const uint4* hl = (const uint4*)(g_hbl + (size_t)gr_a * 128 + c * 32 + ahalf);
            p[0] = va ? hh[0] : z;
            p[1] = va ? hh[1] : z;
            p[2] = va ? hl[0] : z;
            p[3] = va ? hl[1] : z;
        } else {
            int k0 = c * 32;
            int koff = (k0 < 512) ? (k0 - 128) : (k0 < 896 ? k0 - 512 : k0 - 896);
            const float* bp = g_agg + (size_t)gr_a * 384 + koff + ahalf;
            #pragma unroll
            for (int q = 0; q < 4; q++)
                p[q] = va ? *(const uint4*)(bp + q * 4) : z;
        }
    };
    auto fillB = [&](int k0, int st) {
        uint32_t sbase = b_base + (uint32_t)(st * SB_STAGE * 2);
        #pragma unroll
        for (int i = tid; i < BN * 8; i += 256) {
            int img = i >= BN * 4;
            int j   = img ? i - BN * 4 : i;
            int n   = j >> 2, q = j & 3;
            const unsigned short* g = img ? g_Ulo[L] : g_Uhi[L];
            uint32_t daddr = sbase + (uint32_t)(((img * BN + n) * 40 + q * 8) * 2);
            cp_async16(daddr, g + (size_t)n * KTOT + k0 + q * 8);
        }
        CP_COMMIT();
    };

    fillB(0, 0);
    uint4 p[4];
    prefA(0, p);

    for (int kt = 0; kt < NCH; kt++) {
        int k0 = kt * 32;
        // ---- store prefetched A (h: direct copy; agg: convert+scale)
        uint4 Hv[2], Lv[2];
        if (kt < 4) {
            Hv[0] = p[0]; Hv[1] = p[1]; Lv[0] = p[2]; Lv[1] = p[3];
        } else {
            conv16((const float4*)p, ascale(k0), Hv, Lv);
        }
        *(uint4*)&sA[(size_t)arow * 40 + ahalf]              = Hv[0];
        *(uint4*)&sA[(size_t)arow * 40 + ahalf + 8]          = Hv[1];
        *(uint4*)&sA[(size_t)(128 + arow) * 40 + ahalf]      = Lv[0];
        *(uint4*)&sA[(size_t)(128 + arow) * 40 + ahalf + 8]  = Lv[1];
        if (kt + 1 < NCH) { fillB(k0 + 32, (kt + 1) & 1); CP_WAIT1(); }
        else              { CP_WAIT0(); }
        __syncthreads();
        if (kt + 1 < NCH) prefA(kt + 1, p);
        // ---- mma on stage kt&1
        uint32_t bst = b_base + (uint32_t)((kt & 1) * SB_STAGE * 2);
        #pragma unroll
        for (int ks = 0; ks < 2; ks++) {
            uint32_t ah[2][4], al[2][4];
            #pragma unroll
            for (int mt = 0; mt < 2; mt++) {
                uint32_t r = a_base + (uint32_t)(((wm * 32 + mt * 16 + lrow) * 40 + ks * 16 + lcol) * 2);
                ldsm4(ah[mt], r);
                ldsm4(al[mt], r + 128 * 40 * 2);
            }
            uint32_t bf[WNT / 2][4];
            #pragma unroll
            for (int pt = 0; pt < WNT / 2; pt++) {
                uint32_t r = bst + (uint32_t)(((wn * (BN / 2) + pt * 16 + lrow) * 40 + ks * 16 + lcol) * 2);
                ldsm4(bf[pt], r);
            }
            #pragma unroll
            for (int mt = 0; mt < 2; mt++)
                #pragma unroll
                for (int t = 0; t < WNT; t++) {
                    uint32_t b0 = bf[t >> 1][t & 1], b1 = bf[t >> 1][2 + (t & 1)];
                    mma16816(acc[mt][t], ah[mt], b0, b1);
                    mma16816(acc[mt][t], al[mt], b0, b1);
                }
            #pragma unroll
            for (int pt = 0; pt < WNT / 2; pt++) {
                uint32_t r = bst + (uint32_t)(BN * 40 * 2) +
                             (uint32_t)(((wn * (BN / 2) + pt * 16 + lrow) * 40 + ks * 16 + lcol) * 2);
                ldsm4(bf[pt], r);
            }
            #pragma unroll
            for (int mt = 0; mt < 2; mt++)
                #pragma unroll
                for (int t = 0; t < WNT; t++) {
                    uint32_t b0 = bf[t >> 1][t & 1], b1 = bf[t >> 1][2 + (t & 1)];
                    mma16816(acc[mt][t], ah[mt], b0, b1);
                }
        }
        __syncthreads();
    }
    // ---- epilogue: FINAL -> fp32 d_out; else -> hb bf16 hi/lo images
    int gq = lane >> 2, tg = lane & 3;
    #pragma unroll
    for (int mt = 0; mt < 2; mt++) {
        #pragma unroll
        for (int t = 0; t < WNT; t++) {
            int col = wn * (BN / 2) + t * 8 + tg * 2;
            float u0 = Ub[col], u1 = Ub[col + 1];
            int r0 = row0 + wm * 32 + mt * 16 + gq;
            float v0 = acc[mt][t][0] + u0, v1 = acc[mt][t][1] + u1;
            float v2 = acc[mt][t][2] + u0, v3 = acc[mt][t][3] + u1;
            if (RELU) {
                v0 = fmaxf(v0, 0.f); v1 = fmaxf(v1, 0.f);
                v2 = fmaxf(v2, 0.f); v3 = fmaxf(v3, 0.f);
            }
            if (FINAL) {
                float* C = outp;
                if (r0 < M)     *(float2*)&C[(size_t)r0 * BN + col]       = make_float2(v0, v1);
                if (r0 + 8 < M) *(float2*)&C[(size_t)(r0 + 8) * BN + col] = make_float2(v2, v3);
            } else {
                if (r0 < M) {
                    *(uint32_t*)&g_hbh[(size_t)r0 * 128 + col] =
                        (uint32_t)bfh(v0) | ((uint32_t)bfh(v1) << 16);
                    *(uint32_t*)&g_hbl[(size_t)r0 * 128 + col] =
                        (uint32_t)bfl(v0) | ((uint32_t)bfl(v1) << 16);
                }
                if (r0 + 8 < M) {
                    *(uint32_t*)&g_hbh[(size_t)(r0 + 8) * 128 + col] =
                        (uint32_t)bfh(v2) | ((uint32_t)bfh(v3) << 16);
                    *(uint32_t*)&g_hbl[(size_t)(r0 + 8) * 128 + col] =
                        (uint32_t)bfl(v2) | ((uint32_t)bfl(v3) << 16);
                }
            }
        }
    }
}

// ---------------- mma.sync PQ GEMM: A = hb images (pure copy); grid.y: 0->P 1->Q ----
template <int L>
__global__ __launch_bounds__(256, 2) void mma_pq(const float* __restrict__ Mb, int M) {
    constexpr int KTOT = 128, NCH = 4, BN = 128, WNT = 8;
    __shared__ __align__(16) uint16_t sA[2][128][40];
    __shared__ __align__(16) uint16_t sB[2][BN][40];
    int mat = blockIdx.y;
    float* C = mat ? g_Q : g_P;

    int tid = threadIdx.x, lane = tid & 31, wid = tid >> 5;
    int wm = wid & 3, wn = wid >> 2;
    int row0  = blockIdx.x * 128;
    int arow  = tid >> 1, ahalf = (tid & 1) * 16;
    int gr_a  = row0 + arow;
    bool va   = gr_a < M;

    float acc[2][WNT][4];
    #pragma unroll
    for (int mt = 0; mt < 2; mt++)
        #pragma unroll
        for (int t = 0; t < WNT; t++)
            #pragma unroll
            for (int j = 0; j < 4; j++) acc[mt][t][j] = 0.f;

    uint32_t a_base = smem_u32(&sA[0][0][0]);
    uint32_t b_base = smem_u32(&sB[0][0][0]);
    int lrow = lane & 15, lcol = (lane >> 4) * 8;

    for (int kt = 0; kt < NCH; kt++) {
        int k0 = kt * 32;
        // A: straight bf16 copies from hb images
        {
            uint4 z = make_uint4(0, 0, 0, 0);
            const uint4* hh = (const uint4*)(g_hbh + (size_t)gr_a * 128 + k0 + ahalf);
            const uint4* hl = (const uint4*)(g_hbl + (size_t)gr_a * 128 + k0 + ahalf);
            *(uint4*)&sA[0][arow][ahalf]     = va ? hh[0] : z;
            *(uint4*)&sA[0][arow][ahalf + 8] = va ? hh[1] : z;
            *(uint4*)&sA[1][arow][ahalf]     = va ? hl[0] : z;
            *(uint4*)&sA[1][arow][ahalf + 8] = va ? hl[1] : z;
        }
        #pragma unroll
        for (int i = tid; i < BN * 8; i += 256) {
            int img = i >= BN * 4;
            int j   = img ? i - BN * 4 : i;
            int n   = j >> 2, q = j & 3;
            const unsigned short* g = img ? g_PQlo[L] : g_PQhi[L];
            uint4 v = *(const uint4*)(g + (size_t)(mat * 128 + n) * KTOT + k0 + q * 8);
            *(uint4*)&sB[img][n][q * 8] = v;
        }
        __syncthreads();
        #pragma unroll
        for (int ks = 0; ks < 2; ks++) {
            uint32_t ah[2][4], al[2][4];
            #pragma unroll
            for (int mt = 0; mt < 2; mt++) {
                uint32_t r = a_base + (uint32_t)(((wm * 32 + mt * 16 + lrow) * 40 + ks * 16 + lcol) * 2);
                ldsm4(ah[mt], r);
                ldsm4(al[mt], r + 128 * 40 * 2);
            }
            uint32_t bf[WNT / 2][4];
            #pragma unroll
            for (int pt = 0; pt < WNT / 2; pt++) {
                uint32_t r = b_base + (uint32_t)(((wn * 64 + pt * 16 + lrow) * 40 + ks * 16 + lcol) * 2);
                ldsm4(bf[pt], r);
            }
            #pragma unroll
            for (int mt = 0; mt < 2; mt++)
                #pragma unroll
                for (int t = 0; t < WNT; t++) {
                    uint32_t b0 = bf[t >> 1][t & 1], b1 = bf[t >> 1][2 + (t & 1)];
                    mma16816(acc[mt][t], ah[mt], b0, b1);
                    mma16816(acc[mt][t], al[mt], b0, b1);
                }
            #pragma unroll
            for (int pt = 0; pt < WNT / 2; pt++) {
                uint32_t r = b_base + BN * 40 * 2 +
                             (uint32_t)(((wn * 64 + pt * 16 + lrow) * 40 + ks * 16 + lcol) * 2);
                ldsm4(bf[pt], r);
            }
            #pragma unroll
            for (int mt = 0; mt < 2; mt++)
                #pragma unroll
                for (int t = 0; t < WNT; t++) {
                    uint32_t b0 = bf[t >> 1][t & 1], b1 = bf[t >> 1][2 + (t & 1)];
                    mma16816(acc[mt][t], ah[mt], b0, b1);
                }
        }
        __syncthreads();
    }
    int gq = lane >> 2, tg = lane & 3;
    #pragma unroll
    for (int mt = 0; mt < 2; mt++) {
        #pragma unroll
        for (int t = 0; t < WNT; t++) {
            int col = wn * 64 + t * 8 + tg * 2;
            float u0 = mat ? Mb[col] : 0.f;
            float u1 = mat ? Mb[col + 1] : 0.f;
            int r0 = row0 + wm * 32 + mt * 16 + gq;
            if (r0 < M)
                *(float2*)&C[(size_t)r0 * 128 + col] =
                    make_float2(acc[mt][t][0] + u0, acc[mt][t][1] + u1);
            if (r0 + 8 < M)
                *(float2*)&C[(size_t)(r0 + 8) * 128 + col] =
                    make_float2(acc[mt][t][2] + u0, acc[mt][t][3] + u1);
        }
    }
}

// ---------------- CSR aggregation: warp per node, index-ahead prefetch ----------------
__global__ void agg_kernel(int n) {
    int gw   = (blockIdx.x * blockDim.x + threadIdx.x) >> 5;
    int lane = threadIdx.x & 31;
    if (gw >= n) return;
    int s = g_off[gw], e = g_off[gw + 1];
    int c = lane * 4;
    float4 sum = make_float4(0.f, 0.f, 0.f, 0.f);
    float4 mn  = make_float4(1e30f, 1e30f, 1e30f, 1e30f);
    float4 mx  = make_float4(-1e30f, -1e30f, -1e30f, -1e30f);
    int r_next = (s < e) ? __ldg(&g_csr[s]) : 0;
    for (int i = s; i < e; i++) {
        int r = r_next;
        if (i + 1 < e) r_next = __ldg(&g_csr[i + 1]);
        float4 v = *(const float4*)&g_P[(size_t)r * 128 + c];
        sum.x += v.x; sum.y += v.y; sum.z += v.z; sum.w += v.w;
        mn.x = fminf(mn.x, v.x); mn.y = fminf(mn.y, v.y);
        mn.z = fminf(mn.z, v.z); mn.w = fminf(mn.w, v.w);
        mx.x = fmaxf(mx.x, v.x); mx.y = fmaxf(mx.y, v.y);
        mx.z = fmaxf(mx.z, v.z); mx.w = fmaxf(mx.w, v.w);
    }
    float4 q = *(const float4*)&g_Q[(size_t)gw * 128 + c];
    float4 me, on, ox;
    int d = e - s;
    if (d > 0) {
        float inv = 1.0f / (float)d;
        me.x = sum.x * inv + q.x; me.y = sum.y * inv + q.y;
        me.z = sum.z * inv + q.z; me.w = sum.w * inv + q.w;
        on.x = mn.x + q.x; on.y = mn.y + q.y; on.z = mn.z + q.z; on.w = mn.w + q.w;
        ox.x = mx.x + q.x; ox.y = mx.y + q.y; ox.z = mx.z + q.z; ox.w = mx.w + q.w;
    } else {
        me = make_float4(0.f, 0.f, 0.f, 0.f);
        on = me; ox = me;
    }
    *(float4*)&g_agg[(size_t)gw * 384 + c]       = me;
    *(float4*)&g_agg[(size_t)gw * 384 + 128 + c] = on;
    *(float4*)&g_agg[(size_t)gw * 384 + 256 + c] = ox;
}

// ---------------- host launcher ----------------
extern "C" void kernel_launch(void* const* d_in, const int* in_sizes, int n_in,
                              void* d_out, int out_size) {
    const float* x   = (const float*)d_in[0];
    const void*  src = d_in[1];
    const void*  dst = d_in[2];
    const float* M0w = (const float*)d_in[3];
    const float* M0b = (const float*)d_in[4];
    const float* U0w = (const float*)d_in[5];
    const float* U0b = (const float*)d_in[6];
    const float* M1w = (const float*)d_in[7];
    const float* M1b = (const float*)d_in[8];
    const float* U1w = (const float*)d_in[9];
    const float* U1b = (const float*)d_in[10];
    const float* M2w = (const float*)d_in[11];
    const float* M2b = (const float*)d_in[12];
    const float* U2w = (const float*)d_in[13];
    const float* U2b = (const float*)d_in[14];

    int n = in_sizes[0] / 128;
    int e = in_sizes[1];
    if (n > NN) n = NN;
    if (e > NE) e = NE;

    static cudaStream_t s1 = nullptr, s2 = nullptr;
    static cudaEvent_t evStart1 = nullptr, evStart2 = nullptr;
    static cudaEvent_t evCSR = nullptr, evPre = nullptr, evX = nullptr;
    if (s1 == nullptr) {
        cudaStreamCreateWithFlags(&s1, cudaStreamNonBlocking);
        cudaStreamCreateWithFlags(&s2, cudaStreamNonBlocking);
        cudaEventCreateWithFlags(&evStart1, cudaEventDisableTiming);
        cudaEventCreateWithFlags(&evStart2, cudaEventDisableTiming);
        cudaEventCreateWithFlags(&evCSR, cudaEventDisableTiming);
        cudaEventCreateWithFlags(&evPre, cudaEventDisableTiming);
        cudaEventCreateWithFlags(&evX, cudaEventDisableTiming);
    }

    const int UPD_SMEM_H = 20480 + 2 * 2 * 128 * 40 * 2;  // 61440 (BN=128)
    const int UPD_SMEM_L = 20480 + 2 * 2 * 64 * 40 * 2;   // 40960 (BN=64)
    cudaFuncSetAttribute(mma_update<0, 128, true, 0>,
                         cudaFuncAttributeMaxDynamicSharedMemorySize, UPD_SMEM_H);
    cudaFuncSetAttribute(mma_update<0, 128, true, 1>,
                         cudaFuncAttributeMaxDynamicSharedMemorySize, UPD_SMEM_H);
    cudaFuncSetAttribute(mma_update<1, 64, false, 2>,
                         cudaFuncAttributeMaxDynamicSharedMemorySize, UPD_SMEM_L);

    int gE = (e + 255) / 256;
    int gN = (n + 255) / 256;
    int gM = (n + 127) / 128;
    int gA = (n * 32 + 255) / 256;
    int nb = (n + 1023) / 1024;
    int gX = (n * 32 + 255) / 256;  // n*128/4 threads

    // fork
    cudaEventRecord(evStart1, 0);
    cudaStreamWaitEvent(s1, evStart1, 0);
    cudaEventRecord(evStart2, 0);
    cudaStreamWaitEvent(s2, evStart2, 0);

    // s1: CSR build + node scalars
    detect_kernel<<<1, 256, 0, s1>>>(dst, e, n);
    zero_deg<<<gN, 256, 0, s1>>>(n);
    hist_kernel<<<gE, 256, 0, s1>>>(dst, e);
    scan_p1<<<nb, 256, 0, s1>>>(n);
    scan_p2<<<1, 64, 0, s1>>>(nb, n);
    scan_p3<<<nb, 256, 0, s1>>>(n);
    scatter_kernel<<<gE, 256, 0, s1>>>(src, dst, e);
    cudaEventRecord(evCSR, s1);

    // s2: x seed conversion first (pq0 needs it), then all other prepacks
    conv_x<<<gX, 256, 0, s2>>>(x, n);
    cudaEventRecord(evX, s2);
    prepack_upd2<0><<<(1280 * 128 + 255) / 256, 256, 0, s2>>>(U0w, 128);
    prepack_upd2<1><<<(1280 * 128 + 255) / 256, 256, 0, s2>>>(U1w, 128);
    prepack_upd2<2><<<(1280 * 64 + 255) / 256, 256, 0, s2>>>(U2w, 64);
    prepack_pq2<1><<<128, 256, 0, s2>>>(M1w);
    prepack_pq2<2><<<128, 256, 0, s2>>>(M2w);
    cudaEventRecord(evPre, s2);

    // main: layer 0
    prepack_pq2<0><<<128, 256>>>(M0w);
    cudaStreamWaitEvent(0, evX, 0);
    mma_pq<0><<<dim3(gM, 2), 256>>>(M0b, n);
    cudaStreamWaitEvent(0, evCSR, 0);
    agg_kernel<<<gA, 256>>>(n);
    cudaStreamWaitEvent(0, evPre, 0);
    mma_update<0, 128, true, 0><<<gM, 256, UPD_SMEM_H>>>(U0b, nullptr, n);

    // layer 1
    mma_pq<1><<<dim3(gM, 2), 256>>>(M1b, n);
    agg_kernel<<<gA, 256>>>(n);
    mma_update<0, 128, true, 1><<<gM, 256, UPD_SMEM_H>>>(U1b, nullptr, n);

    // layer 2 (final: fp32 d_out, no relu)
    mma_pq<2><<<dim3(gM, 2), 256>>>(M2b, n);
    agg_kernel<<<gA, 256>>>(n);
    mma_update<1, 64, false, 2><<<gM, 256, UPD_SMEM_L>>>(U2b, (float*)d_out, n);
}

// round 11
// speedup vs baseline: 1.1267x; 1.1267x over previous
#include <cuda_runtime.h>
#include <cuda_bf16.h>
#include <cstdint>
#include <math.h>

#define NN 50000
#define NE 800000

// ---------------- scratch (static device globals; no allocation) ----------------
__device__ int   g_is64;
__device__ int   g_deg[NN];
__device__ int   g_off[NN + 1];
__device__ int   g_cur[NN];
__device__ int   g_csr[NE];
__device__ int   g_bsum[64];
__device__ float g_amp[NN];
__device__ float g_att[NN];
__device__ float g_P[NN * 128];
__device__ float g_Q[NN * 128];
__device__ float g_agg[NN * 384];
__device__ float g_h1[NN * 128];
__device__ float g_h2[NN * 128];
// prepacked weights, PER LAYER: PQ [256 rows (P|Q)][128 K], update [N][1280 K]
__device__ unsigned short g_PQhi[3][256 * 128];
__device__ unsigned short g_PQlo[3][256 * 128];
__device__ unsigned short g_Uhi[3][128 * 1280];
__device__ unsigned short g_Ulo[3][128 * 1280];

// ---------------- helpers ----------------
__device__ __forceinline__ uint32_t smem_u32(const void* p) {
    uint32_t a;
    asm("{ .reg .u64 t; cvta.to.shared.u64 t, %1; cvt.u32.u64 %0, t; }"
        : "=r"(a) : "l"(p));
    return a;
}
__device__ __forceinline__ void ldsm4(uint32_t* r, uint32_t addr) {
    asm volatile("ldmatrix.sync.aligned.m8n8.x4.shared.b16 {%0,%1,%2,%3}, [%4];"
                 : "=r"(r[0]), "=r"(r[1]), "=r"(r[2]), "=r"(r[3]) : "r"(addr));
}
__device__ __forceinline__ void mma16816(float* c, const uint32_t* a,
                                         uint32_t b0, uint32_t b1) {
    asm volatile("mma.sync.aligned.m16n8k16.row.col.f32.bf16.bf16.f32 "
                 "{%0,%1,%2,%3}, {%4,%5,%6,%7}, {%8,%9}, {%0,%1,%2,%3};"
                 : "+f"(c[0]), "+f"(c[1]), "+f"(c[2]), "+f"(c[3])
                 : "r"(a[0]), "r"(a[1]), "r"(a[2]), "r"(a[3]), "r"(b0), "r"(b1));
}
__device__ __forceinline__ void cp_async16(uint32_t daddr, const void* gptr) {
    asm volatile("cp.async.cg.shared.global [%0], [%1], 16;"
                 :: "r"(daddr), "l"(gptr));
}
#define CP_COMMIT() asm volatile("cp.async.commit_group;" ::: "memory")
#define CP_WAIT1()  asm volatile("cp.async.wait_group 1;" ::: "memory")
#define CP_WAIT0()  asm volatile("cp.async.wait_group 0;" ::: "memory")

__device__ __forceinline__ uint16_t bfh(float v) {
    return __bfloat16_as_ushort(__float2bfloat16(v));
}
__device__ __forceinline__ uint16_t bfl(float v) {
    __nv_bfloat16 h = __float2bfloat16(v);
    return __bfloat16_as_ushort(__float2bfloat16(v - __bfloat162float(h)));
}

// 16 fp32 -> bf16 hi/lo (scaled), packed as 2+2 uint4
__device__ __forceinline__ void conv16(const float4* f, float s, uint4* Hv, uint4* Lv) {
    uint32_t hw[8], lw[8];
    #pragma unroll
    for (int q = 0; q < 4; q++) {
        float v[4] = {f[q].x * s, f[q].y * s, f[q].z * s, f[q].w * s};
        uint16_t hb[4], lb[4];
        #pragma unroll
        for (int i = 0; i < 4; i++) {
            __nv_bfloat16 h = __float2bfloat16(v[i]);
            float hf        = __bfloat162float(h);
            __nv_bfloat16 l = __float2bfloat16(v[i] - hf);
            hb[i] = __bfloat16_as_ushort(h);
            lb[i] = __bfloat16_as_ushort(l);
        }
        hw[q * 2 + 0] = (uint32_t)hb[0] | ((uint32_t)hb[1] << 16);
        hw[q * 2 + 1] = (uint32_t)hb[2] | ((uint32_t)hb[3] << 16);
        lw[q * 2 + 0] = (uint32_t)lb[0] | ((uint32_t)lb[1] << 16);
        lw[q * 2 + 1] = (uint32_t)lb[2] | ((uint32_t)lb[3] << 16);
    }
    Hv[0] = make_uint4(hw[0], hw[1], hw[2], hw[3]);
    Hv[1] = make_uint4(hw[4], hw[5], hw[6], hw[7]);
    Lv[0] = make_uint4(lw[0], lw[1], lw[2], lw[3]);
    Lv[1] = make_uint4(lw[4], lw[5], lw[6], lw[7]);
}

// ---------------- index-width detection ----------------
__global__ void detect_kernel(const void* dst, int e, int n) {
    __shared__ int bad;
    if (threadIdx.x == 0) bad = 0;
    __syncthreads();
    int k = e < 1024 ? e : 1024;
    const long long* p = (const long long*)dst;
    for (int i = threadIdx.x; i < k; i += blockDim.x) {
        long long v = p[i];
        if (v < 0 || v >= (long long)n) atomicExch(&bad, 1);
    }
    __syncthreads();
    if (threadIdx.x == 0) g_is64 = bad ? 0 : 1;
}
__device__ __forceinline__ int load_idx(const void* p, int i) {
    if (g_is64) return (int)((const long long*)p)[i];
    return ((const int*)p)[i];
}

// ---------------- CSR build ----------------
__global__ void zero_deg(int n) {
    int i = blockIdx.x * blockDim.x + threadIdx.x;
    if (i < n) g_deg[i] = 0;
}
__global__ void hist_kernel(const void* __restrict__ dst, int e) {
    int i = blockIdx.x * blockDim.x + threadIdx.x;
    if (i < e) atomicAdd(&g_deg[load_idx(dst, i)], 1);
}

__global__ void scan_p1(int n) {
    int base = blockIdx.x * 1024 + threadIdx.x * 4;
    int s = 0;
    #pragma unroll
    for (int j = 0; j < 4; j++) {
        int i = base + j;
        if (i < n) s += g_deg[i];
    }
    #pragma unroll
    for (int o = 16; o; o >>= 1) s += __shfl_down_sync(0xFFFFFFFFu, s, o);
    __shared__ int ws[8];
    if ((threadIdx.x & 31) == 0) ws[threadIdx.x >> 5] = s;
    __syncthreads();
    if (threadIdx.x == 0) {
        int t = 0;
        #pragma unroll
        for (int w = 0; w < 8; w++) t += ws[w];
        g_bsum[blockIdx.x] = t;
    }
}
__global__ void scan_p2(int nb, int n) {
    int tid = threadIdx.x;
    int v = tid < nb ? g_bsum[tid] : 0;
    __shared__ int tmp[64];
    tmp[tid] = v;
    __syncthreads();
    #pragma unroll
    for (int o = 1; o < 64; o <<= 1) {
        int t = tid >= o ? tmp[tid - o] : 0;
        __syncthreads();
        tmp[tid] += t;
        __syncthreads();
    }
    if (tid < nb) g_bsum[tid] = tmp[tid] - v;
    if (tid == 0) g_off[n] = tmp[63];
}
__global__ void scan_p3(int n) {
    int tid  = threadIdx.x;
    int base = blockIdx.x * 1024 + tid * 4;
    int d[4], s = 0;
    #pragma unroll
    for (int j = 0; j < 4; j++) {
        int i = base + j;
        d[j] = (i < n) ? g_deg[i] : 0;
        s += d[j];
    }
    int lane = tid & 31, w = tid >> 5;
    int incl = s;
    #pragma unroll
    for (int o = 1; o < 32; o <<= 1) {
        int t = __shfl_up_sync(0xFFFFFFFFu, incl, o);
        if (lane >= o) incl += t;
    }
    __shared__ int ws[8];
    if (lane == 31) ws[w] = incl;
    __syncthreads();
    if (tid == 0) {
        int acc = 0;
        #pragma unroll
        for (int q = 0; q < 8; q++) { int t = ws[q]; ws[q] = acc; acc += t; }
    }
    __syncthreads();
    int run = incl - s + ws[w] + g_bsum[blockIdx.x];
    #pragma unroll
    for (int j = 0; j < 4; j++) {
        int i = base + j;
        if (i < n) {
            g_off[i] = run;
            g_cur[i] = run;
            float ld = logf((float)d[j] + 1.0f);
            g_amp[i] = ld * (1.0f / 3.0f);
            g_att[i] = 3.0f / fmaxf(ld, 1e-6f);
            run += d[j];
        }
    }
}

__global__ void scatter_kernel(const void* __restrict__ src,
                               const void* __restrict__ dst, int e) {
    int i = blockIdx.x * blockDim.x + threadIdx.x;
    if (i < e) {
        int d   = load_idx(dst, i);
        int pos = atomicAdd(&g_cur[d], 1);
        g_csr[pos] = load_idx(src, i);
    }
}

// ---------------- weight prepack (per-layer buffers) ----------------
template <int L>
__global__ void prepack_upd2(const float* __restrict__ Uw, int N) {
    int idx = blockIdx.x * blockDim.x + threadIdx.x;
    if (idx >= 1280 * N) return;
    int k = idx / N, n = idx % N;
    float v = Uw[idx];
    size_t pos = (size_t)n * 1280 + k;
    g_Uhi[L][pos] = bfh(v);
    g_Ulo[L][pos] = bfl(v);
}
template <int L>
__global__ void prepack_pq2(const float* __restrict__ Mw) {
    int idx = blockIdx.x * blockDim.x + threadIdx.x;
    if (idx >= 256 * 128) return;
    int n = idx >> 7, k = idx & 127;
    int mat = n >> 7, nn = n & 127;
    float v = Mw[(mat * 128 + k) * 128 + nn];
    size_t pos = (size_t)n * 128 + k;
    g_PQhi[L][pos] = bfh(v);
    g_PQlo[L][pos] = bfl(v);
}

// ---------------- input selection helper ----------------
template <int SEL>
__device__ __forceinline__ const float* sel_in(const float* a) {
    if constexpr (SEL == 1) return g_h1;
    else if constexpr (SEL == 2) return g_h2;
    else return a;
}

// ---------------- mma.sync update GEMM, cp.async B + A-prefetch pipeline ------
template <int INSEL, int OUTSEL, int BN, bool RELU, int L>
__global__ __launch_bounds__(256, 2) void mma_update(const float* __restrict__ hin,
                                                     const float* __restrict__ Ub,
                                                     float* __restrict__ outp, int M) {
    constexpr int KTOT = 1280, NCH = 40, WNT = BN / 16;
    constexpr int SB_STAGE = 2 * BN * 40;
    extern __shared__ __align__(16) char dyn[];
    uint16_t* sA = (uint16_t*)dyn;            // [2][128][40]
    uint16_t* sB = (uint16_t*)(dyn + 20480);  // [2 stages][2 imgs][BN][40]
    const float* H = sel_in<INSEL>(hin);
    float* C;
    if constexpr (OUTSEL == 1) C = g_h1;
    else if constexpr (OUTSEL == 2) C = g_h2;
    else C = outp;

    int tid = threadIdx.x, lane = tid & 31, wid = tid >> 5;
    int wm = wid & 3, wn = wid >> 2;
    int row0  = blockIdx.x * 128;
    int arow  = tid >> 1, ahalf = (tid & 1) * 16;
    int gr_a  = row0 + arow;
    bool va   = gr_a < M;
    float s_amp = va ? g_amp[gr_a] : 0.f;
    float s_att = va ? g_att[gr_a] : 0.f;

    float acc[2][WNT][4];
    #pragma unroll
    for (int mt = 0; mt < 2; mt++)
        #pragma unroll
        for (int t = 0; t < WNT; t++)
            #pragma unroll
            for (int j = 0; j < 4; j++) acc[mt][t][j] = 0.f;

    uint32_t a_base = smem_u32(sA);
    uint32_t b_base = smem_u32(sB);
    int lrow = lane & 15, lcol = (lane >> 4) * 8;

    auto aptr = [&](int k0) -> const float* {
        if (k0 < 128)      return H + (size_t)gr_a * 128 + k0;
        else if (k0 < 512) return g_agg + (size_t)gr_a * 384 + (k0 - 128);
        else if (k0 < 896) return g_agg + (size_t)gr_a * 384 + (k0 - 512);
        else               return g_agg + (size_t)gr_a * 384 + (k0 - 896);
    };
    auto ascale = [&](int k0) -> float {
        if (k0 < 512) return 1.f;
        else if (k0 < 896) return s_amp;
        else return s_att;
    };
    auto fillB = [&](int k0, int st) {
        uint32_t sbase = b_base + (uint32_t)(st * SB_STAGE * 2);
        #pragma unroll
        for (int i = tid; i < BN * 8; i += 256) {
            int img = i >= BN * 4;
            int j   = img ? i - BN * 4 : i;
            int n   = j >> 2, q = j & 3;
            const unsigned short* g = img ? g_Ulo[L] : g_Uhi[L];
            uint32_t daddr = sbase + (uint32_t)(((img * BN + n) * 40 + q * 8) * 2);
            cp_async16(daddr, g + (size_t)n * KTOT + k0 + q * 8);
        }
        CP_COMMIT();
    };

    // prologue: B stage 0 + A regs for chunk 0
    fillB(0, 0);
    float4 f[4];
    {
        const float* bp = aptr(0);
        #pragma unroll
        for (int q = 0; q < 4; q++)
            f[q] = va ? *(const float4*)(bp + ahalf + q * 4)
                      : make_float4(0.f, 0.f, 0.f, 0.f);
    }

    for (int kt = 0; kt < NCH; kt++) {
        int k0 = kt * 32;
        // ---- convert + store prefetched A
        uint4 Hv[2], Lv[2];
        conv16(f, ascale(k0), Hv, Lv);
        *(uint4*)&sA[(size_t)arow * 40 + ahalf]              = Hv[0];
        *(uint4*)&sA[(size_t)arow * 40 + ahalf + 8]          = Hv[1];
        *(uint4*)&sA[(size_t)(128 + arow) * 40 + ahalf]      = Lv[0];
        *(uint4*)&sA[(size_t)(128 + arow) * 40 + ahalf + 8]  = Lv[1];
        // ---- prefetch next B stage, wait for current
        if (kt + 1 < NCH) { fillB(k0 + 32, (kt + 1) & 1); CP_WAIT1(); }
        else              { CP_WAIT0(); }
        __syncthreads();
        // ---- prefetch next-chunk A (LDG latency hides under MMA below)
        if (kt + 1 < NCH) {
            const float* bp = aptr(k0 + 32);
            #pragma unroll
            for (int q = 0; q < 4; q++)
                f[q] = va ? *(const float4*)(bp + ahalf + q * 4)
                          : make_float4(0.f, 0.f, 0.f, 0.f);
        }
        // ---- mma on stage kt&1
        uint32_t bst = b_base + (uint32_t)((kt & 1) * SB_STAGE * 2);
        #pragma unroll
        for (int ks = 0; ks < 2; ks++) {
            uint32_t ah[2][4], al[2][4];
            #pragma unroll
            for (int mt = 0; mt < 2; mt++) {
                uint32_t r = a_base + (uint32_t)(((wm * 32 + mt * 16 + lrow) * 40 + ks * 16 + lcol) * 2);
                ldsm4(ah[mt], r);
                ldsm4(al[mt], r + 128 * 40 * 2);
            }
            uint32_t bf[WNT / 2][4];
            #pragma unroll
            for (int pt = 0; pt < WNT / 2; pt++) {
                uint32_t r = bst + (uint32_t)(((wn * (BN / 2) + pt * 16 + lrow) * 40 + ks * 16 + lcol) * 2);
                ldsm4(bf[pt], r);
            }
            #pragma unroll
            for (int mt = 0; mt < 2; mt++)
                #pragma unroll
                for (int t = 0; t < WNT; t++) {
                    uint32_t b0 = bf[t >> 1][t & 1], b1 = bf[t >> 1][2 + (t & 1)];
                    mma16816(acc[mt][t], ah[mt], b0, b1);
                    mma16816(acc[mt][t], al[mt], b0, b1);
                }
            #pragma unroll
            for (int pt = 0; pt < WNT / 2; pt++) {
                uint32_t r = bst + (uint32_t)(BN * 40 * 2) +
                             (uint32_t)(((wn * (BN / 2) + pt * 16 + lrow) * 40 + ks * 16 + lcol) * 2);
                ldsm4(bf[pt], r);
            }
            #pragma unroll
            for (int mt = 0; mt < 2; mt++)
                #pragma unroll
                for (int t = 0; t < WNT; t++) {
                    uint32_t b0 = bf[t >> 1][t & 1], b1 = bf[t >> 1][2 + (t & 1)];
                    mma16816(acc[mt][t], ah[mt], b0, b1);
                }
        }
        __syncthreads();
    }
    // ---- epilogue
    int gq = lane >> 2, tg = lane & 3;
    #pragma unroll
    for (int mt = 0; mt < 2; mt++) {
        #pragma unroll
        for (int t = 0; t < WNT; t++) {
            int col = wn * (BN / 2) + t * 8 + tg * 2;
            float u0 = Ub[col], u1 = Ub[col + 1];
            int r0 = row0 + wm * 32 + mt * 16 + gq;
            float v0 = acc[mt][t][0] + u0, v1 = acc[mt][t][1] + u1;
            float v2 = acc[mt][t][2] + u0, v3 = acc[mt][t][3] + u1;
            if (RELU) {
                v0 = fmaxf(v0, 0.f); v1 = fmaxf(v1, 0.f);
                v2 = fmaxf(v2, 0.f); v3 = fmaxf(v3, 0.f);
            }
            if (r0 < M)     *(float2*)&C[(size_t)r0 * BN + col]       = make_float2(v0, v1);
            if (r0 + 8 < M) *(float2*)&C[(size_t)(r0 + 8) * BN + col] = make_float2(v2, v3);
        }
    }
}

// ---------------- mma.sync PQ GEMM: grid.y=0 -> P, 1 -> Q(+Mb) ----------------
template <int INSEL, int L>
__global__ __launch_bounds__(256, 2) void mma_pq(const float* __restrict__ hin,
                                                 const float* __restrict__ Mb, int M) {
    constexpr int KTOT = 128, NCH = 4, BN = 128, WNT = 8;
    __shared__ __align__(16) uint16_t sA[2][128][40];
    __shared__ __align__(16) uint16_t sB[2][BN][40];
    const float* H = sel_in<INSEL>(hin);
    int mat = blockIdx.y;
    float* C = mat ? g_Q : g_P;

    int tid = threadIdx.x, lane = tid & 31, wid = tid >> 5;
    int wm = wid & 3, wn = wid >> 2;
    int row0  = blockIdx.x * 128;
    int arow  = tid >> 1, ahalf = (tid & 1) * 16;
    int gr_a  = row0 + arow;
    bool va   = gr_a < M;

    float acc[2][WNT][4];
    #pragma unroll
    for (int mt = 0; mt < 2; mt++)
        #pragma unroll
        for (int t = 0; t < WNT; t++)
            #pragma unroll
            for (int j = 0; j < 4; j++) acc[mt][t][j] = 0.f;

    uint32_t a_base = smem_u32(&sA[0][0][0]);
    uint32_t b_base = smem_u32(&sB[0][0][0]);
    int lrow = lane & 15, lcol = (lane >> 4) * 8;

    for (int kt = 0; kt < NCH; kt++) {
        int k0 = kt * 32;
        const float* bp = H + (size_t)gr_a * 128 + k0;
        float4 f[4];
        #pragma unroll
        for (int q = 0; q < 4; q++)
            f[q] = va ? *(const float4*)(bp + ahalf + q * 4)
                      : make_float4(0.f, 0.f, 0.f, 0.f);
        uint4 Hv[2], Lv[2];
        conv16(f, 1.0f, Hv, Lv);
        *(uint4*)&sA[0][arow][ahalf]     = Hv[0];
        *(uint4*)&sA[0][arow][ahalf + 8] = Hv[1];
        *(uint4*)&sA[1][arow][ahalf]     = Lv[0];
        *(uint4*)&sA[1][arow][ahalf + 8] = Lv[1];
        #pragma unroll
        for (int i = tid; i < BN * 8; i += 256) {
            int img = i >= BN * 4;
            int j   = img ? i - BN * 4 : i;
            int n   = j >> 2, q = j & 3;
            const unsigned short* g = img ? g_PQlo[L] : g_PQhi[L];
            uint4 v = *(const uint4*)(g + (size_t)(mat * 128 + n) * KTOT + k0 + q * 8);
            *(uint4*)&sB[img][n][q * 8] = v;
        }
        __syncthreads();
        #pragma unroll
        for (int ks = 0; ks < 2; ks++) {
            uint32_t ah[2][4], al[2][4];
            #pragma unroll
            for (int mt = 0; mt < 2; mt++) {
                uint32_t r = a_base + (uint32_t)(((wm * 32 + mt * 16 + lrow) * 40 + ks * 16 + lcol) * 2);
                ldsm4(ah[mt], r);
                ldsm4(al[mt], r + 128 * 40 * 2);
            }
            uint32_t bf[WNT / 2][4];
            #pragma unroll
            for (int pt = 0; pt < WNT / 2; pt++) {
                uint32_t r = b_base + (uint32_t)(((wn * 64 + pt * 16 + lrow) * 40 + ks * 16 + lcol) * 2);
                ldsm4(bf[pt], r);
            }
            #pragma unroll
            for (int mt = 0; mt < 2; mt++)
                #pragma unroll
                for (int t = 0; t < WNT; t++) {
                    uint32_t b0 = bf[t >> 1][t & 1], b1 = bf[t >> 1][2 + (t & 1)];
                    mma16816(acc[mt][t], ah[mt], b0, b1);
                    mma16816(acc[mt][t], al[mt], b0, b1);
                }
            #pragma unroll
            for (int pt = 0; pt < WNT / 2; pt++) {
                uint32_t r = b_base + BN * 40 * 2 +
                             (uint32_t)(((wn * 64 + pt * 16 + lrow) * 40 + ks * 16 + lcol) * 2);
                ldsm4(bf[pt], r);
            }
            #pragma unroll
            for (int mt = 0; mt < 2; mt++)
                #pragma unroll
                for (int t = 0; t < WNT; t++) {
                    uint32_t b0 = bf[t >> 1][t & 1], b1 = bf[t >> 1][2 + (t & 1)];
                    mma16816(acc[mt][t], ah[mt], b0, b1);
                }
        }
        __syncthreads();
    }
    int gq = lane >> 2, tg = lane & 3;
    #pragma unroll
    for (int mt = 0; mt < 2; mt++) {
        #pragma unroll
        for (int t = 0; t < WNT; t++) {
            int col = wn * 64 + t * 8 + tg * 2;
            float u0 = mat ? Mb[col] : 0.f;
            float u1 = mat ? Mb[col + 1] : 0.f;
            int r0 = row0 + wm * 32 + mt * 16 + gq;
            if (r0 < M)
                *(float2*)&C[(size_t)r0 * 128 + col] =
                    make_float2(acc[mt][t][0] + u0, acc[mt][t][1] + u1);
            if (r0 + 8 < M)
                *(float2*)&C[(size_t)(r0 + 8) * 128 + col] =
                    make_float2(acc[mt][t][2] + u0, acc[mt][t][3] + u1);
        }
    }
}

// ---------------- CSR aggregation: warp per node, manual 2-way unroll ----------------
__global__ void agg_kernel(int n) {
    int gw   = (blockIdx.x * blockDim.x + threadIdx.x) >> 5;
    int lane = threadIdx.x & 31;
    if (gw >= n) return;
    int s = g_off[gw], e = g_off[gw + 1];
    int c = lane * 4;
    float4 sum = make_float4(0.f, 0.f, 0.f, 0.f);
    float4 mn  = make_float4(1e30f, 1e30f, 1e30f, 1e30f);
    float4 mx  = make_float4(-1e30f, -1e30f, -1e30f, -1e30f);
    int i = s;
    for (; i + 2 <= e; i += 2) {
        int r0 = g_csr[i], r1 = g_csr[i + 1];
        float4 v0 = *(const float4*)&g_P[(size_t)r0 * 128 + c];
        float4 v1 = *(const float4*)&g_P[(size_t)r1 * 128 + c];
        sum.x += v0.x + v1.x; sum.y += v0.y + v1.y;
        sum.z += v0.z + v1.z; sum.w += v0.w + v1.w;
        mn.x = fminf(mn.x, fminf(v0.x, v1.x)); mn.y = fminf(mn.y, fminf(v0.y, v1.y));
        mn.z = fminf(mn.z, fminf(v0.z, v1.z)); mn.w = fminf(mn.w, fminf(v0.w, v1.w));
        mx.x = fmaxf(mx.x, fmaxf(v0.x, v1.x)); mx.y = fmaxf(mx.y, fmaxf(v0.y, v1.y));
        mx.z = fmaxf(mx.z, fmaxf(v0.z, v1.z)); mx.w = fmaxf(mx.w, fmaxf(v0.w, v1.w));
    }
    if (i < e) {
        int r = g_csr[i];
        float4 v = *(const float4*)&g_P[(size_t)r * 128 + c];
        sum.x += v.x; sum.y += v.y; sum.z += v.z; sum.w += v.w;
        mn.x = fminf(mn.x, v.x); mn.y = fminf(mn.y, v.y);
        mn.z = fminf(mn.z, v.z); mn.w = fminf(mn.w, v.w);
        mx.x = fmaxf(mx.x, v.x); mx.y = fmaxf(mx.y, v.y);
        mx.z = fmaxf(mx.z, v.z); mx.w = fmaxf(mx.w, v.w);
    }
    float4 q = *(const float4*)&g_Q[(size_t)gw * 128 + c];
    float4 me, on, ox;
    int d = e - s;
    if (d > 0) {
        float inv = 1.0f / (float)d;
        me.x = sum.x * inv + q.x; me.y = sum.y * inv + q.y;
        me.z = sum.z * inv + q.z; me.w = sum.w * inv + q.w;
        on.x = mn.x + q.x; on.y = mn.y + q.y; on.z = mn.z + q.z; on.w = mn.w + q.w;
        ox.x = mx.x + q.x; ox.y = mx.y + q.y; ox.z = mx.z + q.z; ox.w = mx.w + q.w;
    } else {
        me = make_float4(0.f, 0.f, 0.f, 0.f);
        on = me; ox = me;
    }
    *(float4*)&g_agg[(size_t)gw * 384 + c]       = me;
    *(float4*)&g_agg[(size_t)gw * 384 + 128 + c] = on;
    *(float4*)&g_agg[(size_t)gw * 384 + 256 + c] = ox;
}

// ---------------- host launcher ----------------
extern "C" void kernel_launch(void* const* d_in, const int* in_sizes, int n_in,
                              void* d_out, int out_size) {
    const float* x   = (const float*)d_in[0];
    const void*  src = d_in[1];
    const void*  dst = d_in[2];
    const float* M0w = (const float*)d_in[3];
    const float* M0b = (const float*)d_in[4];
    const float* U0w = (const float*)d_in[5];
    const float* U0b = (const float*)d_in[6];
    const float* M1w = (const float*)d_in[7];
    const float* M1b = (const float*)d_in[8];
    const float* U1w = (const float*)d_in[9];
    const float* U1b = (const float*)d_in[10];
    const float* M2w = (const float*)d_in[11];
    const float* M2b = (const float*)d_in[12];
    const float* U2w = (const float*)d_in[13];
    const float* U2b = (const float*)d_in[14];

    int n = in_sizes[0] / 128;
    int e = in_sizes[1];
    if (n > NN) n = NN;
    if (e > NE) e = NE;

    static cudaStream_t s1 = nullptr, s2 = nullptr;
    static cudaEvent_t evStart1 = nullptr, evStart2 = nullptr, evCSR = nullptr, evPre = nullptr;
    if (s1 == nullptr) {
        cudaStreamCreateWithFlags(&s1, cudaStreamNonBlocking);
        cudaStreamCreateWithFlags(&s2, cudaStreamNonBlocking);
        cudaEventCreateWithFlags(&evStart1, cudaEventDisableTiming);
        cudaEventCreateWithFlags(&evStart2, cudaEventDisableTiming);
        cudaEventCreateWithFlags(&evCSR, cudaEventDisableTiming);
        cudaEventCreateWithFlags(&evPre, cudaEventDisableTiming);
    }

    const int UPD_SMEM_H = 20480 + 2 * 2 * 128 * 40 * 2;  // 61440 (BN=128)
    const int UPD_SMEM_L = 20480 + 2 * 2 * 64 * 40 * 2;   // 40960 (BN=64)
    cudaFuncSetAttribute(mma_update<0, 1, 128, true, 0>,
                         cudaFuncAttributeMaxDynamicSharedMemorySize, UPD_SMEM_H);
    cudaFuncSetAttribute(mma_update<1, 2, 128, true, 1>,
                         cudaFuncAttributeMaxDynamicSharedMemorySize, UPD_SMEM_H);
    cudaFuncSetAttribute(mma_update<2, 0, 64, false, 2>,
                         cudaFuncAttributeMaxDynamicSharedMemorySize, UPD_SMEM_L);

    int gE = (e + 255) / 256;
    int gN = (n + 255) / 256;
    int gM = (n + 127) / 128;
    int gA = (n * 32 + 255) / 256;
    int nb = (n + 1023) / 1024;

    // fork: s1 = CSR build, s2 = remaining prepacks; main starts layer-0 PQ
    cudaEventRecord(evStart1, 0);
    cudaStreamWaitEvent(s1, evStart1, 0);
    cudaEventRecord(evStart2, 0);
    cudaStreamWaitEvent(s2, evStart2, 0);

    // s1: CSR build + node scalars
    detect_kernel<<<1, 256, 0, s1>>>(dst, e, n);
    zero_deg<<<gN, 256, 0, s1>>>(n);
    hist_kernel<<<gE, 256, 0, s1>>>(dst, e);
    scan_p1<<<nb, 256, 0, s1>>>(n);
    scan_p2<<<1, 64, 0, s1>>>(nb, n);
    scan_p3<<<nb, 256, 0, s1>>>(n);
    scatter_kernel<<<gE, 256, 0, s1>>>(src, dst, e);
    cudaEventRecord(evCSR, s1);

    // s2: all update prepacks + later-layer PQ prepacks
    prepack_upd2<0><<<(1280 * 128 + 255) / 256, 256, 0, s2>>>(U0w, 128);
    prepack_upd2<1><<<(1280 * 128 + 255) / 256, 256, 0, s2>>>(U1w, 128);
    prepack_upd2<2><<<(1280 * 64 + 255) / 256, 256, 0, s2>>>(U2w, 64);
    prepack_pq2<1><<<128, 256, 0, s2>>>(M1w);
    prepack_pq2<2><<<128, 256, 0, s2>>>(M2w);
    cudaEventRecord(evPre, s2);

    // main: layer 0 PQ (needs only its own prepack)
    prepack_pq2<0><<<128, 256>>>(M0w);
    mma_pq<0, 0><<<dim3(gM, 2), 256>>>(x, M0b, n);
    cudaStreamWaitEvent(0, evCSR, 0);   // agg needs CSR
    agg_kernel<<<gA, 256>>>(n);
    cudaStreamWaitEvent(0, evPre, 0);   // update needs its prepack
    mma_update<0, 1, 128, true, 0><<<gM, 256, UPD_SMEM_H>>>(x, U0b, nullptr, n);

    // layer 1
    mma_pq<1, 1><<<dim3(gM, 2), 256>>>(nullptr, M1b, n);
    agg_kernel<<<gA, 256>>>(n);
    mma_update<1, 2, 128, true, 1><<<gM, 256, UPD_SMEM_H>>>(nullptr, U1b, nullptr, n);

    // layer 2 (N=64, no relu)
    mma_pq<2, 2><<<dim3(gM, 2), 256>>>(nullptr, M2b, n);
    agg_kernel<<<gA, 256>>>(n);
    mma_update<2, 0, 64, false, 2><<<gM, 256, UPD_SMEM_L>>>(nullptr, U2b, (float*)d_out, n);
}

// round 12
// speedup vs baseline: 1.1546x; 1.0248x over previous
#include <cuda_runtime.h>
#include <cuda_bf16.h>
#include <cstdint>
#include <math.h>

#define NN 50000
#define NE 800000

// ---------------- scratch (static device globals; no allocation) ----------------
__device__ int   g_is64;
__device__ int   g_deg[NN];
__device__ int   g_off[NN + 1];
__device__ int   g_cur[NN];
__device__ int   g_csr[NE];
__device__ int   g_bsum[64];
__device__ float g_amp[NN];
__device__ float g_att[NN];
__device__ float g_P[NN * 128];
__device__ float g_Q[NN * 128];
__device__ float g_agg[NN * 384];
__device__ float g_h1[NN * 128];
__device__ float g_h2[NN * 128];
// prepacked weights, PER LAYER: PQ [256 rows (P|Q)][128 K], update [N][1280 K perm]
__device__ unsigned short g_PQhi[3][256 * 128];
__device__ unsigned short g_PQlo[3][256 * 128];
__device__ unsigned short g_Uhi[3][128 * 1280];
__device__ unsigned short g_Ulo[3][128 * 1280];

// ---------------- helpers ----------------
__device__ __forceinline__ uint32_t smem_u32(const void* p) {
    uint32_t a;
    asm("{ .reg .u64 t; cvta.to.shared.u64 t, %1; cvt.u32.u64 %0, t; }"
        : "=r"(a) : "l"(p));
    return a;
}
__device__ __forceinline__ void ldsm4(uint32_t* r, uint32_t addr) {
    asm volatile("ldmatrix.sync.aligned.m8n8.x4.shared.b16 {%0,%1,%2,%3}, [%4];"
                 : "=r"(r[0]), "=r"(r[1]), "=r"(r[2]), "=r"(r[3]) : "r"(addr));
}
__device__ __forceinline__ void mma16816(float* c, const uint32_t* a,
                                         uint32_t b0, uint32_t b1) {
    asm volatile("mma.sync.aligned.m16n8k16.row.col.f32.bf16.bf16.f32 "
                 "{%0,%1,%2,%3}, {%4,%5,%6,%7}, {%8,%9}, {%0,%1,%2,%3};"
                 : "+f"(c[0]), "+f"(c[1]), "+f"(c[2]), "+f"(c[3])
                 : "r"(a[0]), "r"(a[1]), "r"(a[2]), "r"(a[3]), "r"(b0), "r"(b1));
}
__device__ __forceinline__ void cp_async16(uint32_t daddr, const void* gptr) {
    asm volatile("cp.async.cg.shared.global [%0], [%1], 16;"
                 :: "r"(daddr), "l"(gptr));
}
#define CP_COMMIT() asm volatile("cp.async.commit_group;" ::: "memory")
#define CP_WAIT1()  asm volatile("cp.async.wait_group 1;" ::: "memory")
#define CP_WAIT0()  asm volatile("cp.async.wait_group 0;" ::: "memory")

__device__ __forceinline__ uint16_t bfh(float v) {
    return __bfloat16_as_ushort(__float2bfloat16(v));
}
__device__ __forceinline__ uint16_t bfl(float v) {
    __nv_bfloat16 h = __float2bfloat16(v);
    return __bfloat16_as_ushort(__float2bfloat16(v - __bfloat162float(h)));
}

// 16 fp32 -> bf16 hi/lo (scaled), packed as 2+2 uint4
__device__ __forceinline__ void conv16(const float4* f, float s, uint4* Hv, uint4* Lv) {
    uint32_t hw[8], lw[8];
    #pragma unroll
    for (int q = 0; q < 4; q++) {
        float v[4] = {f[q].x * s, f[q].y * s, f[q].z * s, f[q].w * s};
        uint16_t hb[4], lb[4];
        #pragma unroll
        for (int i = 0; i < 4; i++) {
            __nv_bfloat16 h = __float2bfloat16(v[i]);
            float hf        = __bfloat162float(h);
            __nv_bfloat16 l = __float2bfloat16(v[i] - hf);
            hb[i] = __bfloat16_as_ushort(h);
            lb[i] = __bfloat16_as_ushort(l);
        }
        hw[q * 2 + 0] = (uint32_t)hb[0] | ((uint32_t)hb[1] << 16);
        hw[q * 2 + 1] = (uint32_t)hb[2] | ((uint32_t)hb[3] << 16);
        lw[q * 2 + 0] = (uint32_t)lb[0] | ((uint32_t)lb[1] << 16);
        lw[q * 2 + 1] = (uint32_t)lb[2] | ((uint32_t)lb[3] << 16);
    }
    Hv[0] = make_uint4(hw[0], hw[1], hw[2], hw[3]);
    Hv[1] = make_uint4(hw[4], hw[5], hw[6], hw[7]);
    Lv[0] = make_uint4(lw[0], lw[1], lw[2], lw[3]);
    Lv[1] = make_uint4(lw[4], lw[5], lw[6], lw[7]);
}

// ---------------- index-width detection ----------------
__global__ void detect_kernel(const void* dst, int e, int n) {
    __shared__ int bad;
    if (threadIdx.x == 0) bad = 0;
    __syncthreads();
    int k = e < 1024 ? e : 1024;
    const long long* p = (const long long*)dst;
    for (int i = threadIdx.x; i < k; i += blockDim.x) {
        long long v = p[i];
        if (v < 0 || v >= (long long)n) atomicExch(&bad, 1);
    }
    __syncthreads();
    if (threadIdx.x == 0) g_is64 = bad ? 0 : 1;
}
__device__ __forceinline__ int load_idx(const void* p, int i) {
    if (g_is64) return (int)((const long long*)p)[i];
    return ((const int*)p)[i];
}

// ---------------- CSR build ----------------
__global__ void zero_deg(int n) {
    int i = blockIdx.x * blockDim.x + threadIdx.x;
    if (i < n) g_deg[i] = 0;
}
__global__ void hist_kernel(const void* __restrict__ dst, int e) {
    int i = blockIdx.x * blockDim.x + threadIdx.x;
    if (i < e) atomicAdd(&g_deg[load_idx(dst, i)], 1);
}

__global__ void scan_p1(int n) {
    int base = blockIdx.x * 1024 + threadIdx.x * 4;
    int s = 0;
    #pragma unroll
    for (int j = 0; j < 4; j++) {
        int i = base + j;
        if (i < n) s += g_deg[i];
    }
    #pragma unroll
    for (int o = 16; o; o >>= 1) s += __shfl_down_sync(0xFFFFFFFFu, s, o);
    __shared__ int ws[8];
    if ((threadIdx.x & 31) == 0) ws[threadIdx.x >> 5] = s;
    __syncthreads();
    if (threadIdx.x == 0) {
        int t = 0;
        #pragma unroll
        for (int w = 0; w < 8; w++) t += ws[w];
        g_bsum[blockIdx.x] = t;
    }
}
__global__ void scan_p2(int nb, int n) {
    int tid = threadIdx.x;
    int v = tid < nb ? g_bsum[tid] : 0;
    __shared__ int tmp[64];
    tmp[tid] = v;
    __syncthreads();
    #pragma unroll
    for (int o = 1; o < 64; o <<= 1) {
        int t = tid >= o ? tmp[tid - o] : 0;
        __syncthreads();
        tmp[tid] += t;
        __syncthreads();
    }
    if (tid < nb) g_bsum[tid] = tmp[tid] - v;
    if (tid == 0) g_off[n] = tmp[63];
}
__global__ void scan_p3(int n) {
    int tid  = threadIdx.x;
    int base = blockIdx.x * 1024 + tid * 4;
    int d[4], s = 0;
    #pragma unroll
    for (int j = 0; j < 4; j++) {
        int i = base + j;
        d[j] = (i < n) ? g_deg[i] : 0;
        s += d[j];
    }
    int lane = tid & 31, w = tid >> 5;
    int incl = s;
    #pragma unroll
    for (int o = 1; o < 32; o <<= 1) {
        int t = __shfl_up_sync(0xFFFFFFFFu, incl, o);
        if (lane >= o) incl += t;
    }
    __shared__ int ws[8];
    if (lane == 31) ws[w] = incl;
    __syncthreads();
    if (tid == 0) {
        int acc = 0;
        #pragma unroll
        for (int q = 0; q < 8; q++) { int t = ws[q]; ws[q] = acc; acc += t; }
    }
    __syncthreads();
    int run = incl - s + ws[w] + g_bsum[blockIdx.x];
    #pragma unroll
    for (int j = 0; j < 4; j++) {
        int i = base + j;
        if (i < n) {
            g_off[i] = run;
            g_cur[i] = run;
            float ld = logf((float)d[j] + 1.0f);
            g_amp[i] = ld * (1.0f / 3.0f);
            g_att[i] = 3.0f / fmaxf(ld, 1e-6f);
            run += d[j];
        }
    }
}

__global__ void scatter_kernel(const void* __restrict__ src,
                               const void* __restrict__ dst, int e) {
    int i = blockIdx.x * blockDim.x + threadIdx.x;
    if (i < e) {
        int d   = load_idx(dst, i);
        int pos = atomicAdd(&g_cur[d], 1);
        g_csr[pos] = load_idx(src, i);
    }
}

// ---------------- weight prepack (per-layer buffers) ----------------
// update: K-permuted layout: [h(0..127) | for j=0..11: (agg_j, agg_j*amp, agg_j*att)]
// original k: agg k=128+m, amp k=512+m, att k=896+m (m in 0..383)
// new k for (j = m/32, r = m%32, variant v): 128 + (j*3 + v)*32 + r
template <int L>
__global__ void prepack_upd2(const float* __restrict__ Uw, int N) {
    int idx = blockIdx.x * blockDim.x + threadIdx.x;
    if (idx >= 1280 * N) return;
    int k = idx / N, n = idx % N;
    float v = Uw[idx];
    int knew;
    if (k < 128) {
        knew = k;
    } else {
        int m, var;
        if (k < 512)      { m = k - 128; var = 0; }
        else if (k < 896) { m = k - 512; var = 1; }
        else              { m = k - 896; var = 2; }
        int j = m >> 5, r = m & 31;
        knew = 128 + ((j * 3 + var) << 5) + r;
    }
    size_t pos = (size_t)n * 1280 + knew;
    g_Uhi[L][pos] = bfh(v);
    g_Ulo[L][pos] = bfl(v);
}
template <int L>
__global__ void prepack_pq2(const float* __restrict__ Mw) {
    int idx = blockIdx.x * blockDim.x + threadIdx.x;
    if (idx >= 256 * 128) return;
    int n = idx >> 7, k = idx & 127;
    int mat = n >> 7, nn = n & 127;
    float v = Mw[(mat * 128 + k) * 128 + nn];
    size_t pos = (size_t)n * 128 + k;
    g_PQhi[L][pos] = bfh(v);
    g_PQlo[L][pos] = bfl(v);
}

// ---------------- input selection helper ----------------
template <int SEL>
__device__ __forceinline__ const float* sel_in(const float* a) {
    if constexpr (SEL == 1) return g_h1;
    else if constexpr (SEL == 2) return g_h2;
    else return a;
}

// ---------------- mma.sync update GEMM, cp.async B + dedup'd A pipeline ------
template <int INSEL, int OUTSEL, int BN, bool RELU, int L>
__global__ __launch_bounds__(256, 2) void mma_update(const float* __restrict__ hin,
                                                     const float* __restrict__ Ub,
                                                     float* __restrict__ outp, int M) {
    constexpr int KTOT = 1280, NCH = 40, WNT = BN / 16;
    constexpr int SB_STAGE = 2 * BN * 40;
    extern __shared__ __align__(16) char dyn[];
    uint16_t* sA = (uint16_t*)dyn;            // [2][128][40]
    uint16_t* sB = (uint16_t*)(dyn + 20480);  // [2 stages][2 imgs][BN][40]
    const float* H = sel_in<INSEL>(hin);
    float* C;
    if constexpr (OUTSEL == 1) C = g_h1;
    else if constexpr (OUTSEL == 2) C = g_h2;
    else C = outp;

    int tid = threadIdx.x, lane = tid & 31, wid = tid >> 5;
    int wm = wid & 3, wn = wid >> 2;
    int row0  = blockIdx.x * 128;
    int arow  = tid >> 1, ahalf = (tid & 1) * 16;
    int gr_a  = row0 + arow;
    bool va   = gr_a < M;
    float s_amp = va ? g_amp[gr_a] : 0.f;
    float s_att = va ? g_att[gr_a] : 0.f;

    float acc[2][WNT][4];
    #pragma unroll
    for (int mt = 0; mt < 2; mt++)
        #pragma unroll
        for (int t = 0; t < WNT; t++)
            #pragma unroll
            for (int j = 0; j < 4; j++) acc[mt][t][j] = 0.f;

    uint32_t a_base = smem_u32(sA);
    uint32_t b_base = smem_u32(sB);
    int lrow = lane & 15, lcol = (lane >> 4) * 8;

    // chunk c: c<4 -> h chunk c; else j=(c-4)/3 agg chunk, variant (c-4)%3
    auto srcA = [&](int c) -> const float* {
        if (c < 4) return H + (size_t)gr_a * 128 + c * 32;
        int j = (c - 4) / 3;
        return g_agg + (size_t)gr_a * 384 + j * 32;
    };
    auto needload = [&](int c) -> bool {
        return c < 4 || ((c - 4) % 3) == 0;
    };
    auto cscale = [&](int c) -> float {
        if (c < 4) return 1.f;
        int v = (c - 4) % 3;
        return v == 0 ? 1.f : (v == 1 ? s_amp : s_att);
    };
    auto fillB = [&](int k0, int st) {
        uint32_t sbase = b_base + (uint32_t)(st * SB_STAGE * 2);
        #pragma unroll
        for (int i = tid; i < BN * 8; i += 256) {
            int img = i >= BN * 4;
            int j   = img ? i - BN * 4 : i;
            int n   = j >> 2, q = j & 3;
            const unsigned short* g = img ? g_Ulo[L] : g_Uhi[L];
            uint32_t daddr = sbase + (uint32_t)(((img * BN + n) * 40 + q * 8) * 2);
            cp_async16(daddr, g + (size_t)n * KTOT + k0 + q * 8);
        }
        CP_COMMIT();
    };

    // prologue: B stage 0 + A regs for chunk 0
    fillB(0, 0);
    float4 f[4];
    {
        const float* bp = srcA(0);
        #pragma unroll
        for (int q = 0; q < 4; q++)
            f[q] = va ? *(const float4*)(bp + ahalf + q * 4)
                      : make_float4(0.f, 0.f, 0.f, 0.f);
    }

    for (int kt = 0; kt < NCH; kt++) {
        int k0 = kt * 32;
        // ---- convert + store A (f holds source data for this chunk)
        uint4 Hv[2], Lv[2];
        conv16(f, cscale(kt), Hv, Lv);
        *(uint4*)&sA[(size_t)arow * 40 + ahalf]              = Hv[0];
        *(uint4*)&sA[(size_t)arow * 40 + ahalf + 8]          = Hv[1];
        *(uint4*)&sA[(size_t)(128 + arow) * 40 + ahalf]      = Lv[0];
        *(uint4*)&sA[(size_t)(128 + arow) * 40 + ahalf + 8]  = Lv[1];
        // ---- prefetch next B stage, wait for current
        if (kt + 1 < NCH) { fillB(k0 + 32, (kt + 1) & 1); CP_WAIT1(); }
        else              { CP_WAIT0(); }
        __syncthreads();
        // ---- load next-chunk A only when its source differs (LDG hides under MMA)
        if (kt + 1 < NCH && needload(kt + 1)) {
            const float* bp = srcA(kt + 1);
            #pragma unroll
            for (int q = 0; q < 4; q++)
                f[q] = va ? *(const float4*)(bp + ahalf + q * 4)
                          : make_float4(0.f, 0.f, 0.f, 0.f);
        }
        // ---- mma on stage kt&1
        uint32_t bst = b_base + (uint32_t)((kt & 1) * SB_STAGE * 2);
        #pragma unroll
        for (int ks = 0; ks < 2; ks++) {
            uint32_t ah[2][4], al[2][4];
            #pragma unroll
            for (int mt = 0; mt < 2; mt++) {
                uint32_t r = a_base + (uint32_t)(((wm * 32 + mt * 16 + lrow) * 40 + ks * 16 + lcol) * 2);
                ldsm4(ah[mt], r);
                ldsm4(al[mt], r + 128 * 40 * 2);
            }
            uint32_t bf[WNT / 2][4];
            #pragma unroll
            for (int pt = 0; pt < WNT / 2; pt++) {
                uint32_t r = bst + (uint32_t)(((wn * (BN / 2) + pt * 16 + lrow) * 40 + ks * 16 + lcol) * 2);
                ldsm4(bf[pt], r);
            }
            #pragma unroll
            for (int mt = 0; mt < 2; mt++)
                #pragma unroll
                for (int t = 0; t < WNT; t++) {
                    uint32_t b0 = bf[t >> 1][t & 1], b1 = bf[t >> 1][2 + (t & 1)];
                    mma16816(acc[mt][t], ah[mt], b0, b1);
                    mma16816(acc[mt][t], al[mt], b0, b1);
                }
            #pragma unroll
            for (int pt = 0; pt < WNT / 2; pt++) {
                uint32_t r = bst + (uint32_t)(BN * 40 * 2) +
                             (uint32_t)(((wn * (BN / 2) + pt * 16 + lrow) * 40 + ks * 16 + lcol) * 2);
                ldsm4(bf[pt], r);
            }
            #pragma unroll
            for (int mt = 0; mt < 2; mt++)
                #pragma unroll
                for (int t = 0; t < WNT; t++) {
                    uint32_t b0 = bf[t >> 1][t & 1], b1 = bf[t >> 1][2 + (t & 1)];
                    mma16816(acc[mt][t], ah[mt], b0, b1);
                }
        }
        __syncthreads();
    }
    // ---- epilogue
    int gq = lane >> 2, tg = lane & 3;
    #pragma unroll
    for (int mt = 0; mt < 2; mt++) {
        #pragma unroll
        for (int t = 0; t < WNT; t++) {
            int col = wn * (BN / 2) + t * 8 + tg * 2;
            float u0 = Ub[col], u1 = Ub[col + 1];
            int r0 = row0 + wm * 32 + mt * 16 + gq;
            float v0 = acc[mt][t][0] + u0, v1 = acc[mt][t][1] + u1;
            float v2 = acc[mt][t][2] + u0, v3 = acc[mt][t][3] + u1;
            if (RELU) {
                v0 = fmaxf(v0, 0.f); v1 = fmaxf(v1, 0.f);
                v2 = fmaxf(v2, 0.f); v3 = fmaxf(v3, 0.f);
            }
            if (r0 < M)     *(float2*)&C[(size_t)r0 * BN + col]       = make_float2(v0, v1);
            if (r0 + 8 < M) *(float2*)&C[(size_t)(r0 + 8) * BN + col] = make_float2(v2, v3);
        }
    }
}

// ---------------- mma.sync PQ GEMM, cp.async double-buffered B ----------------
// grid.y=0 -> P, 1 -> Q(+Mb); dyn smem: sA [2][128][40] | sB [2 st][2 imgs][128][40]
template <int INSEL, int L>
__global__ __launch_bounds__(256, 2) void mma_pq(const float* __restrict__ hin,
                                                 const float* __restrict__ Mb, int M) {
    constexpr int KTOT = 128, NCH = 4, BN = 128, WNT = 8;
    constexpr int SB_STAGE = 2 * BN * 40;
    extern __shared__ __align__(16) char dyn[];
    uint16_t* sA = (uint16_t*)dyn;
    uint16_t* sB = (uint16_t*)(dyn + 20480);
    const float* H = sel_in<INSEL>(hin);
    int mat = blockIdx.y;
    float* C = mat ? g_Q : g_P;

    int tid = threadIdx.x, lane = tid & 31, wid = tid >> 5;
    int wm = wid & 3, wn = wid >> 2;
    int row0  = blockIdx.x * 128;
    int arow  = tid >> 1, ahalf = (tid & 1) * 16;
    int gr_a  = row0 + arow;
    bool va   = gr_a < M;

    float acc[2][WNT][4];
    #pragma unroll
    for (int mt = 0; mt < 2; mt++)
        #pragma unroll
        for (int t = 0; t < WNT; t++)
            #pragma unroll
            for (int j = 0; j < 4; j++) acc[mt][t][j] = 0.f;

    uint32_t a_base = smem_u32(sA);
    uint32_t b_base = smem_u32(sB);
    int lrow = lane & 15, lcol = (lane >> 4) * 8;

    auto fillB = [&](int k0, int st) {
        uint32_t sbase = b_base + (uint32_t)(st * SB_STAGE * 2);
        #pragma unroll
        for (int i = tid; i < BN * 8; i += 256) {
            int img = i >= BN * 4;
            int j   = img ? i - BN * 4 : i;
            int n   = j >> 2, q = j & 3;
            const unsigned short* g = img ? g_PQlo[L] : g_PQhi[L];
            uint32_t daddr = sbase + (uint32_t)(((img * BN + n) * 40 + q * 8) * 2);
            cp_async16(daddr, g + (size_t)(mat * 128 + n) * KTOT + k0 + q * 8);
        }
        CP_COMMIT();
    };

    fillB(0, 0);
    float4 f[4];
    {
        const float* bp = H + (size_t)gr_a * 128;
        #pragma unroll
        for (int q = 0; q < 4; q++)
            f[q] = va ? *(const float4*)(bp + ahalf + q * 4)
                      : make_float4(0.f, 0.f, 0.f, 0.f);
    }

    for (int kt = 0; kt < NCH; kt++) {
        int k0 = kt * 32;
        uint4 Hv[2], Lv[2];
        conv16(f, 1.0f, Hv, Lv);
        *(uint4*)&sA[(size_t)arow * 40 + ahalf]              = Hv[0];
        *(uint4*)&sA[(size_t)arow * 40 + ahalf + 8]          = Hv[1];
        *(uint4*)&sA[(size_t)(128 + arow) * 40 + ahalf]      = Lv[0];
        *(uint4*)&sA[(size_t)(128 + arow) * 40 + ahalf + 8]  = Lv[1];
        if (kt + 1 < NCH) { fillB(k0 + 32, (kt + 1) & 1); CP_WAIT1(); }
        else              { CP_WAIT0(); }
        __syncthreads();
        if (kt + 1 < NCH) {
            const float* bp = H + (size_t)gr_a * 128 + (k0 + 32);
            #pragma unroll
            for (int q = 0; q < 4; q++)
                f[q] = va ? *(const float4*)(bp + ahalf + q * 4)
                          : make_float4(0.f, 0.f, 0.f, 0.f);
        }
        uint32_t bst = b_base + (uint32_t)((kt & 1) * SB_STAGE * 2);
        #pragma unroll
        for (int ks = 0; ks < 2; ks++) {
            uint32_t ah[2][4], al[2][4];
            #pragma unroll
            for (int mt = 0; mt < 2; mt++) {
                uint32_t r = a_base + (uint32_t)(((wm * 32 + mt * 16 + lrow) * 40 + ks * 16 + lcol) * 2);
                ldsm4(ah[mt], r);
                ldsm4(al[mt], r + 128 * 40 * 2);
            }
            uint32_t bf[WNT / 2][4];
            #pragma unroll
            for (int pt = 0; pt < WNT / 2; pt++) {
                uint32_t r = bst + (uint32_t)(((wn * 64 + pt * 16 + lrow) * 40 + ks * 16 + lcol) * 2);
                ldsm4(bf[pt], r);
            }
            #pragma unroll
            for (int mt = 0; mt < 2; mt++)
                #pragma unroll
                for (int t = 0; t < WNT; t++) {
                    uint32_t b0 = bf[t >> 1][t & 1], b1 = bf[t >> 1][2 + (t & 1)];
                    mma16816(acc[mt][t], ah[mt], b0, b1);
                    mma16816(acc[mt][t], al[mt], b0, b1);
                }
            #pragma unroll
            for (int pt = 0; pt < WNT / 2; pt++) {
                uint32_t r = bst + (uint32_t)(BN * 40 * 2) +
                             (uint32_t)(((wn * 64 + pt * 16 + lrow) * 40 + ks * 16 + lcol) * 2);
                ldsm4(bf[pt], r);
            }
            #pragma unroll
            for (int mt = 0; mt < 2; mt++)
                #pragma unroll
                for (int t = 0; t < WNT; t++) {
                    uint32_t b0 = bf[t >> 1][t & 1], b1 = bf[t >> 1][2 + (t & 1)];
                    mma16816(acc[mt][t], ah[mt], b0, b1);
                }
        }
        __syncthreads();
    }
    int gq = lane >> 2, tg = lane & 3;
    #pragma unroll
    for (int mt = 0; mt < 2; mt++) {
        #pragma unroll
        for (int t = 0; t < WNT; t++) {
            int col = wn * 64 + t * 8 + tg * 2;
            float u0 = mat ? Mb[col] : 0.f;
            float u1 = mat ? Mb[col + 1] : 0.f;
            int r0 = row0 + wm * 32 + mt * 16 + gq;
            if (r0 < M)
                *(float2*)&C[(size_t)r0 * 128 + col] =
                    make_float2(acc[mt][t][0] + u0, acc[mt][t][1] + u1);
            if (r0 + 8 < M)
                *(float2*)&C[(size_t)(r0 + 8) * 128 + col] =
                    make_float2(acc[mt][t][2] + u0, acc[mt][t][3] + u1);
        }
    }
}

// ---------------- CSR aggregation: warp per node, manual 2-way unroll ----------------
__global__ void agg_kernel(int n) {
    int gw   = (blockIdx.x * blockDim.x + threadIdx.x) >> 5;
    int lane = threadIdx.x & 31;
    if (gw >= n) return;
    int s = g_off[gw], e = g_off[gw + 1];
    int c = lane * 4;
    float4 sum = make_float4(0.f, 0.f, 0.f, 0.f);
    float4 mn  = make_float4(1e30f, 1e30f, 1e30f, 1e30f);
    float4 mx  = make_float4(-1e30f, -1e30f, -1e30f, -1e30f);
    int i = s;
    for (; i + 2 <= e; i += 2) {
        int r0 = g_csr[i], r1 = g_csr[i + 1];
        float4 v0 = *(const float4*)&g_P[(size_t)r0 * 128 + c];
        float4 v1 = *(const float4*)&g_P[(size_t)r1 * 128 + c];
        sum.x += v0.x + v1.x; sum.y += v0.y + v1.y;
        sum.z += v0.z + v1.z; sum.w += v0.w + v1.w;
        mn.x = fminf(mn.x, fminf(v0.x, v1.x)); mn.y = fminf(mn.y, fminf(v0.y, v1.y));
        mn.z = fminf(mn.z, fminf(v0.z, v1.z)); mn.w = fminf(mn.w, fminf(v0.w, v1.w));
        mx.x = fmaxf(mx.x, fmaxf(v0.x, v1.x)); mx.y = fmaxf(mx.y, fmaxf(v0.y, v1.y));
        mx.z = fmaxf(mx.z, fmaxf(v0.z, v1.z)); mx.w = fmaxf(mx.w, fmaxf(v0.w, v1.w));
    }
    if (i < e) {
        int r = g_csr[i];
        float4 v = *(const float4*)&g_P[(size_t)r * 128 + c];
        sum.x += v.x; sum.y += v.y; sum.z += v.z; sum.w += v.w;
        mn.x = fminf(mn.x, v.x); mn.y = fminf(mn.y, v.y);
        mn.z = fminf(mn.z, v.z); mn.w = fminf(mn.w, v.w);
        mx.x = fmaxf(mx.x, v.x); mx.y = fmaxf(mx.y, v.y);
        mx.z = fmaxf(mx.z, v.z); mx.w = fmaxf(mx.w, v.w);
    }
    float4 q = *(const float4*)&g_Q[(size_t)gw * 128 + c];
    float4 me, on, ox;
    int d = e - s;
    if (d > 0) {
        float inv = 1.0f / (float)d;
        me.x = sum.x * inv + q.x; me.y = sum.y * inv + q.y;
        me.z = sum.z * inv + q.z; me.w = sum.w * inv + q.w;
        on.x = mn.x + q.x; on.y = mn.y + q.y; on.z = mn.z + q.z; on.w = mn.w + q.w;
        ox.x = mx.x + q.x; ox.y = mx.y + q.y; ox.z = mx.z + q.z; ox.w = mx.w + q.w;
    } else {
        me = make_float4(0.f, 0.f, 0.f, 0.f);
        on = me; ox = me;
    }
    *(float4*)&g_agg[(size_t)gw * 384 + c]       = me;
    *(float4*)&g_agg[(size_t)gw * 384 + 128 + c] = on;
    *(float4*)&g_agg[(size_t)gw * 384 + 256 + c] = ox;
}

// ---------------- host launcher ----------------
extern "C" void kernel_launch(void* const* d_in, const int* in_sizes, int n_in,
                              void* d_out, int out_size) {
    const float* x   = (const float*)d_in[0];
    const void*  src = d_in[1];
    const void*  dst = d_in[2];
    const float* M0w = (const float*)d_in[3];
    const float* M0b = (const float*)d_in[4];
    const float* U0w = (const float*)d_in[5];
    const float* U0b = (const float*)d_in[6];
    const float* M1w = (const float*)d_in[7];
    const float* M1b = (const float*)d_in[8];
    const float* U1w = (const float*)d_in[9];
    const float* U1b = (const float*)d_in[10];
    const float* M2w = (const float*)d_in[11];
    const float* M2b = (const float*)d_in[12];
    const float* U2w = (const float*)d_in[13];
    const float* U2b = (const float*)d_in[14];

    int n = in_sizes[0] / 128;
    int e = in_sizes[1];
    if (n > NN) n = NN;
    if (e > NE) e = NE;

    static cudaStream_t s1 = nullptr, s2 = nullptr;
    static cudaEvent_t evStart1 = nullptr, evStart2 = nullptr, evCSR = nullptr, evPre = nullptr;
    if (s1 == nullptr) {
        cudaStreamCreateWithFlags(&s1, cudaStreamNonBlocking);
        cudaStreamCreateWithFlags(&s2, cudaStreamNonBlocking);
        cudaEventCreateWithFlags(&evStart1, cudaEventDisableTiming);
        cudaEventCreateWithFlags(&evStart2, cudaEventDisableTiming);
        cudaEventCreateWithFlags(&evCSR, cudaEventDisableTiming);
        cudaEventCreateWithFlags(&evPre, cudaEventDisableTiming);
    }

    const int UPD_SMEM_H = 20480 + 2 * 2 * 128 * 40 * 2;  // 61440 (BN=128)
    const int UPD_SMEM_L = 20480 + 2 * 2 * 64 * 40 * 2;   // 40960 (BN=64)
    const int PQ_SMEM    = 20480 + 2 * 2 * 128 * 40 * 2;  // 61440
    cudaFuncSetAttribute(mma_update<0, 1, 128, true, 0>,
                         cudaFuncAttributeMaxDynamicSharedMemorySize, UPD_SMEM_H);
    cudaFuncSetAttribute(mma_update<1, 2, 128, true, 1>,
                         cudaFuncAttributeMaxDynamicSharedMemorySize, UPD_SMEM_H);
    cudaFuncSetAttribute(mma_update<2, 0, 64, false, 2>,
                         cudaFuncAttributeMaxDynamicSharedMemorySize, UPD_SMEM_L);
    cudaFuncSetAttribute(mma_pq<0, 0>,
                         cudaFuncAttributeMaxDynamicSharedMemorySize, PQ_SMEM);
    cudaFuncSetAttribute(mma_pq<1, 1>,
                         cudaFuncAttributeMaxDynamicSharedMemorySize, PQ_SMEM);
    cudaFuncSetAttribute(mma_pq<2, 2>,
                         cudaFuncAttributeMaxDynamicSharedMemorySize, PQ_SMEM);

    int gE = (e + 255) / 256;
    int gN = (n + 255) / 256;
    int gM = (n + 127) / 128;
    int gA = (n * 32 + 255) / 256;
    int nb = (n + 1023) / 1024;

    // fork: s1 = CSR build, s2 = remaining prepacks; main starts layer-0 PQ
    cudaEventRecord(evStart1, 0);
    cudaStreamWaitEvent(s1, evStart1, 0);
    cudaEventRecord(evStart2, 0);
    cudaStreamWaitEvent(s2, evStart2, 0);

    // s1: CSR build + node scalars
    detect_kernel<<<1, 256, 0, s1>>>(dst, e, n);
    zero_deg<<<gN, 256, 0, s1>>>(n);
    hist_kernel<<<gE, 256, 0, s1>>>(dst, e);
    scan_p1<<<nb, 256, 0, s1>>>(n);
    scan_p2<<<1, 64, 0, s1>>>(nb, n);
    scan_p3<<<nb, 256, 0, s1>>>(n);
    scatter_kernel<<<gE, 256, 0, s1>>>(src, dst, e);
    cudaEventRecord(evCSR, s1);

    // s2: all update prepacks + later-layer PQ prepacks
    prepack_upd2<0><<<(1280 * 128 + 255) / 256, 256, 0, s2>>>(U0w, 128);
    prepack_upd2<1><<<(1280 * 128 + 255) / 256, 256, 0, s2>>>(U1w, 128);
    prepack_upd2<2><<<(1280 * 64 + 255) / 256, 256, 0, s2>>>(U2w, 64);
    prepack_pq2<1><<<128, 256, 0, s2>>>(M1w);
    prepack_pq2<2><<<128, 256, 0, s2>>>(M2w);
    cudaEventRecord(evPre, s2);

    // main: layer 0 PQ (needs only its own prepack)
    prepack_pq2<0><<<128, 256>>>(M0w);
    mma_pq<0, 0><<<dim3(gM, 2), 256, PQ_SMEM>>>(x, M0b, n);
    cudaStreamWaitEvent(0, evCSR, 0);   // agg needs CSR
    agg_kernel<<<gA, 256>>>(n);
    cudaStreamWaitEvent(0, evPre, 0);   // update needs its prepack
    mma_update<0, 1, 128, true, 0><<<gM, 256, UPD_SMEM_H>>>(x, U0b, nullptr, n);

    // layer 1
    mma_pq<1, 1><<<dim3(gM, 2), 256, PQ_SMEM>>>(nullptr, M1b, n);
    agg_kernel<<<gA, 256>>>(n);
    mma_update<1, 2, 128, true, 1><<<gM, 256, UPD_SMEM_H>>>(nullptr, U1b, nullptr, n);

    // layer 2 (N=64, no relu)
    mma_pq<2, 2><<<dim3(gM, 2), 256, PQ_SMEM>>>(nullptr, M2b, n);
    agg_kernel<<<gA, 256>>>(n);
    mma_update<2, 0, 64, false, 2><<<gM, 256, UPD_SMEM_L>>>(nullptr, U2b, (float*)d_out, n);
}

// round 13
// speedup vs baseline: 1.1644x; 1.0085x over previous
#include <cuda_runtime.h>
#include <cuda_bf16.h>
#include <cstdint>
#include <math.h>

#define NN 50000
#define NE 800000

// ---------------- scratch (static device globals; no allocation) ----------------
__device__ int   g_is64;
__device__ int   g_deg[NN];
__device__ int   g_off[NN + 1];
__device__ int   g_cur[NN];
__device__ int   g_csr[NE];
__device__ int   g_bsum[64];
__device__ float g_amp[NN];
__device__ float g_att[NN];
__device__ float g_P[NN * 128];
__device__ float g_Q[NN * 128];
__device__ float g_agg[NN * 384];
__device__ float g_h1[NN * 128];
__device__ float g_h2[NN * 128];
// prepacked weights, PER LAYER: PQ [256 rows (P|Q)][128 K], update [N][1280 K perm]
__device__ unsigned short g_PQhi[3][256 * 128];
__device__ unsigned short g_PQlo[3][256 * 128];
__device__ unsigned short g_Uhi[3][128 * 1280];
__device__ unsigned short g_Ulo[3][128 * 1280];

// ---------------- helpers ----------------
__device__ __forceinline__ uint32_t smem_u32(const void* p) {
    uint32_t a;
    asm("{ .reg .u64 t; cvta.to.shared.u64 t, %1; cvt.u32.u64 %0, t; }"
        : "=r"(a) : "l"(p));
    return a;
}
__device__ __forceinline__ void ldsm4(uint32_t* r, uint32_t addr) {
    asm volatile("ldmatrix.sync.aligned.m8n8.x4.shared.b16 {%0,%1,%2,%3}, [%4];"
                 : "=r"(r[0]), "=r"(r[1]), "=r"(r[2]), "=r"(r[3]) : "r"(addr));
}
__device__ __forceinline__ void mma16816(float* c, const uint32_t* a,
                                         uint32_t b0, uint32_t b1) {
    asm volatile("mma.sync.aligned.m16n8k16.row.col.f32.bf16.bf16.f32 "
                 "{%0,%1,%2,%3}, {%4,%5,%6,%7}, {%8,%9}, {%0,%1,%2,%3};"
                 : "+f"(c[0]), "+f"(c[1]), "+f"(c[2]), "+f"(c[3])
                 : "r"(a[0]), "r"(a[1]), "r"(a[2]), "r"(a[3]), "r"(b0), "r"(b1));
}
__device__ __forceinline__ void cp_async16(uint32_t daddr, const void* gptr) {
    asm volatile("cp.async.cg.shared.global [%0], [%1], 16;"
                 :: "r"(daddr), "l"(gptr));
}
#define CP_COMMIT() asm volatile("cp.async.commit_group;" ::: "memory")
#define CP_WAIT1()  asm volatile("cp.async.wait_group 1;" ::: "memory")
#define CP_WAIT0()  asm volatile("cp.async.wait_group 0;" ::: "memory")

__device__ __forceinline__ uint16_t bfh(float v) {
    return __bfloat16_as_ushort(__float2bfloat16(v));
}
__device__ __forceinline__ uint16_t bfl(float v) {
    __nv_bfloat16 h = __float2bfloat16(v);
    return __bfloat16_as_ushort(__float2bfloat16(v - __bfloat162float(h)));
}

// 16 fp32 -> bf16 hi/lo (scaled), packed as 2+2 uint4
__device__ __forceinline__ void conv16(const float4* f, float s, uint4* Hv, uint4* Lv) {
    uint32_t hw[8], lw[8];
    #pragma unroll
    for (int q = 0; q < 4; q++) {
        float v[4] = {f[q].x * s, f[q].y * s, f[q].z * s, f[q].w * s};
        uint16_t hb[4], lb[4];
        #pragma unroll
        for (int i = 0; i < 4; i++) {
            __nv_bfloat16 h = __float2bfloat16(v[i]);
            float hf        = __bfloat162float(h);
            __nv_bfloat16 l = __float2bfloat16(v[i] - hf);
            hb[i] = __bfloat16_as_ushort(h);
            lb[i] = __bfloat16_as_ushort(l);
        }
        hw[q * 2 + 0] = (uint32_t)hb[0] | ((uint32_t)hb[1] << 16);
        hw[q * 2 + 1] = (uint32_t)hb[2] | ((uint32_t)hb[3] << 16);
        lw[q * 2 + 0] = (uint32_t)lb[0] | ((uint32_t)lb[1] << 16);
        lw[q * 2 + 1] = (uint32_t)lb[2] | ((uint32_t)lb[3] << 16);
    }
    Hv[0] = make_uint4(hw[0], hw[1], hw[2], hw[3]);
    Hv[1] = make_uint4(hw[4], hw[5], hw[6], hw[7]);
    Lv[0] = make_uint4(lw[0], lw[1], lw[2], lw[3]);
    Lv[1] = make_uint4(lw[4], lw[5], lw[6], lw[7]);
}

// ---------------- index-width detection ----------------
__global__ void detect_kernel(const void* dst, int e, int n) {
    __shared__ int bad;
    if (threadIdx.x == 0) bad = 0;
    __syncthreads();
    int k = e < 1024 ? e : 1024;
    const long long* p = (const long long*)dst;
    for (int i = threadIdx.x; i < k; i += blockDim.x) {
        long long v = p[i];
        if (v < 0 || v >= (long long)n) atomicExch(&bad, 1);
    }
    __syncthreads();
    if (threadIdx.x == 0) g_is64 = bad ? 0 : 1;
}
__device__ __forceinline__ int load_idx(const void* p, int i) {
    if (g_is64) return (int)((const long long*)p)[i];
    return ((const int*)p)[i];
}

// ---------------- CSR build ----------------
__global__ void zero_deg(int n) {
    int i = blockIdx.x * blockDim.x + threadIdx.x;
    if (i < n) g_deg[i] = 0;
}
__global__ void hist_kernel(const void* __restrict__ dst, int e) {
    int i = blockIdx.x * blockDim.x + threadIdx.x;
    if (i < e) atomicAdd(&g_deg[load_idx(dst, i)], 1);
}

__global__ void scan_p1(int n) {
    int base = blockIdx.x * 1024 + threadIdx.x * 4;
    int s = 0;
    #pragma unroll
    for (int j = 0; j < 4; j++) {
        int i = base + j;
        if (i < n) s += g_deg[i];
    }
    #pragma unroll
    for (int o = 16; o; o >>= 1) s += __shfl_down_sync(0xFFFFFFFFu, s, o);
    __shared__ int ws[8];
    if ((threadIdx.x & 31) == 0) ws[threadIdx.x >> 5] = s;
    __syncthreads();
    if (threadIdx.x == 0) {
        int t = 0;
        #pragma unroll
        for (int w = 0; w < 8; w++) t += ws[w];
        g_bsum[blockIdx.x] = t;
    }
}
__global__ void scan_p2(int nb, int n) {
    int tid = threadIdx.x;
    int v = tid < nb ? g_bsum[tid] : 0;
    __shared__ int tmp[64];
    tmp[tid] = v;
    __syncthreads();
    #pragma unroll
    for (int o = 1; o < 64; o <<= 1) {
        int t = tid >= o ? tmp[tid - o] : 0;
        __syncthreads();
        tmp[tid] += t;
        __syncthreads();
    }
    if (tid < nb) g_bsum[tid] = tmp[tid] - v;
    if (tid == 0) g_off[n] = tmp[63];
}
__global__ void scan_p3(int n) {
    int tid  = threadIdx.x;
    int base = blockIdx.x * 1024 + tid * 4;
    int d[4], s = 0;
    #pragma unroll
    for (int j = 0; j < 4; j++) {
        int i = base + j;
        d[j] = (i < n) ? g_deg[i] : 0;
        s += d[j];
    }
    int lane = tid & 31, w = tid >> 5;
    int incl = s;
    #pragma unroll
    for (int o = 1; o < 32; o <<= 1) {
        int t = __shfl_up_sync(0xFFFFFFFFu, incl, o);
        if (lane >= o) incl += t;
    }
    __shared__ int ws[8];
    if (lane == 31) ws[w] = incl;
    __syncthreads();
    if (tid == 0) {
        int acc = 0;
        #pragma unroll
        for (int q = 0; q < 8; q++) { int t = ws[q]; ws[q] = acc; acc += t; }
    }
    __syncthreads();
    int run = incl - s + ws[w] + g_bsum[blockIdx.x];
    #pragma unroll
    for (int j = 0; j < 4; j++) {
        int i = base + j;
        if (i < n) {
            g_off[i] = run;
            g_cur[i] = run;
            float ld = logf((float)d[j] + 1.0f);
            g_amp[i] = ld * (1.0f / 3.0f);
            g_att[i] = 3.0f / fmaxf(ld, 1e-6f);
            run += d[j];
        }
    }
}

__global__ void scatter_kernel(const void* __restrict__ src,
                               const void* __restrict__ dst, int e) {
    int i = blockIdx.x * blockDim.x + threadIdx.x;
    if (i < e) {
        int d   = load_idx(dst, i);
        int pos = atomicAdd(&g_cur[d], 1);
        g_csr[pos] = load_idx(src, i);
    }
}

// ---------------- weight prepack (per-layer buffers) ----------------
// update: K-permuted layout: [h(0..127) | for j=0..11: (agg_j, agg_j*amp, agg_j*att)]
template <int L>
__global__ void prepack_upd2(const float* __restrict__ Uw, int N) {
    int idx = blockIdx.x * blockDim.x + threadIdx.x;
    if (idx >= 1280 * N) return;
    int k = idx / N, n = idx % N;
    float v = Uw[idx];
    int knew;
    if (k < 128) {
        knew = k;
    } else {
        int m, var;
        if (k < 512)      { m = k - 128; var = 0; }
        else if (k < 896) { m = k - 512; var = 1; }
        else              { m = k - 896; var = 2; }
        int j = m >> 5, r = m & 31;
        knew = 128 + ((j * 3 + var) << 5) + r;
    }
    size_t pos = (size_t)n * 1280 + knew;
    g_Uhi[L][pos] = bfh(v);
    g_Ulo[L][pos] = bfl(v);
}
template <int L>
__global__ void prepack_pq2(const float* __restrict__ Mw) {
    int idx = blockIdx.x * blockDim.x + threadIdx.x;
    if (idx >= 256 * 128) return;
    int n = idx >> 7, k = idx & 127;
    int mat = n >> 7, nn = n & 127;
    float v = Mw[(mat * 128 + k) * 128 + nn];
    size_t pos = (size_t)n * 128 + k;
    g_PQhi[L][pos] = bfh(v);
    g_PQlo[L][pos] = bfl(v);
}

// ---------------- input selection helper ----------------
template <int SEL>
__device__ __forceinline__ const float* sel_in(const float* a) {
    if constexpr (SEL == 1) return g_h1;
    else if constexpr (SEL == 2) return g_h2;
    else return a;
}

// ---------------- mma.sync update GEMM: 3-stage B, 2-stage A, 1 sync/chunk ----
template <int INSEL, int OUTSEL, int BN, bool RELU, int L>
__global__ __launch_bounds__(256, 2) void mma_update(const float* __restrict__ hin,
                                                     const float* __restrict__ Ub,
                                                     float* __restrict__ outp, int M) {
    constexpr int KTOT = 1280, NCH = 40, WNT = BN / 16;
    constexpr int SA_STAGE = 2 * 128 * 40;   // uint16 units per A stage (hi+lo)
    constexpr int SB_STAGE = 2 * BN * 40;    // uint16 units per B stage (hi+lo)
    extern __shared__ __align__(16) char dyn[];
    uint16_t* sA = (uint16_t*)dyn;                         // [2 stages]
    uint16_t* sB = (uint16_t*)(dyn + 2 * SA_STAGE * 2);    // [3 stages]
    const float* H = sel_in<INSEL>(hin);
    float* C;
    if constexpr (OUTSEL == 1) C = g_h1;
    else if constexpr (OUTSEL == 2) C = g_h2;
    else C = outp;

    int tid = threadIdx.x, lane = tid & 31, wid = tid >> 5;
    int wm = wid & 3, wn = wid >> 2;
    int row0  = blockIdx.x * 128;
    int arow  = tid >> 1, ahalf = (tid & 1) * 16;
    int gr_a  = row0 + arow;
    bool va   = gr_a < M;
    float s_amp = va ? g_amp[gr_a] : 0.f;
    float s_att = va ? g_att[gr_a] : 0.f;

    float acc[2][WNT][4];
    #pragma unroll
    for (int mt = 0; mt < 2; mt++)
        #pragma unroll
        for (int t = 0; t < WNT; t++)
            #pragma unroll
            for (int j = 0; j < 4; j++) acc[mt][t][j] = 0.f;

    uint32_t a_base = smem_u32(sA);
    uint32_t b_base = smem_u32(sB);
    int lrow = lane & 15, lcol = (lane >> 4) * 8;

    auto srcA = [&](int c) -> const float* {
        if (c < 4) return H + (size_t)gr_a * 128 + c * 32;
        int j = (c - 4) / 3;
        return g_agg + (size_t)gr_a * 384 + j * 32;
    };
    auto needload = [&](int c) -> bool {
        return c < 4 || ((c - 4) % 3) == 0;
    };
    auto cscale = [&](int c) -> float {
        if (c < 4) return 1.f;
        int v = (c - 4) % 3;
        return v == 0 ? 1.f : (v == 1 ? s_amp : s_att);
    };
    auto fillB = [&](int c) {
        int k0 = c * 32, st = c % 3;
        uint32_t sbase = b_base + (uint32_t)(st * SB_STAGE * 2);
        #pragma unroll
        for (int i = tid; i < BN * 8; i += 256) {
            int img = i >= BN * 4;
            int j   = img ? i - BN * 4 : i;
            int n   = j >> 2, q = j & 3;
            const unsigned short* g = img ? g_Ulo[L] : g_Uhi[L];
            uint32_t daddr = sbase + (uint32_t)(((img * BN + n) * 40 + q * 8) * 2);
            cp_async16(daddr, g + (size_t)n * KTOT + k0 + q * 8);
        }
        CP_COMMIT();
    };
    auto storeA = [&](int c, const float4* f) {
        uint4 Hv[2], Lv[2];
        conv16(f, cscale(c), Hv, Lv);
        uint16_t* base = sA + (size_t)(c & 1) * SA_STAGE;
        *(uint4*)&base[(size_t)arow * 40 + ahalf]             = Hv[0];
        *(uint4*)&base[(size_t)arow * 40 + ahalf + 8]         = Hv[1];
        *(uint4*)&base[(size_t)(128 + arow) * 40 + ahalf]     = Lv[0];
        *(uint4*)&base[(size_t)(128 + arow) * 40 + ahalf + 8] = Lv[1];
    };

    // prologue: B chunks 0,1 in flight; A chunk 0 stored in stage 0
    fillB(0);
    fillB(1);
    float4 f[4];
    {
        const float* bp = srcA(0);
        #pragma unroll
        for (int q = 0; q < 4; q++)
            f[q] = va ? *(const float4*)(bp + ahalf + q * 4)
                      : make_float4(0.f, 0.f, 0.f, 0.f);
    }
    storeA(0, f);

    for (int kt = 0; kt < NCH; kt++) {
        if (kt == NCH - 1) CP_WAIT0(); else CP_WAIT1();   // B(kt) landed
        __syncthreads();                                   // single barrier per chunk
        if (kt + 2 < NCH) fillB(kt + 2);                   // stage last read by mma(kt-1)
        if (kt + 1 < NCH && needload(kt + 1)) {
            const float* bp = srcA(kt + 1);
            #pragma unroll
            for (int q = 0; q < 4; q++)
                f[q] = va ? *(const float4*)(bp + ahalf + q * 4)
                          : make_float4(0.f, 0.f, 0.f, 0.f);
        }
        // ---- mma on sB stage kt%3, sA stage kt&1
        uint32_t ast = a_base + (uint32_t)((kt & 1) * SA_STAGE * 2);
        uint32_t bst = b_base + (uint32_t)((kt % 3) * SB_STAGE * 2);
        #pragma unroll
        for (int ks = 0; ks < 2; ks++) {
            uint32_t ah[2][4], al[2][4];
            #pragma unroll
            for (int mt = 0; mt < 2; mt++) {
                uint32_t r = ast + (uint32_t)(((wm * 32 + mt * 16 + lrow) * 40 + ks * 16 + lcol) * 2);
                ldsm4(ah[mt], r);
                ldsm4(al[mt], r + 128 * 40 * 2);
            }
            uint32_t bf[WNT / 2][4];
            #pragma unroll
            for (int pt = 0; pt < WNT / 2; pt++) {
                uint32_t r = bst + (uint32_t)(((wn * (BN / 2) + pt * 16 + lrow) * 40 + ks * 16 + lcol) * 2);
                ldsm4(bf[pt], r);
            }
            #pragma unroll
            for (int mt = 0; mt < 2; mt++)
                #pragma unroll
                for (int t = 0; t < WNT; t++) {
                    uint32_t b0 = bf[t >> 1][t & 1], b1 = bf[t >> 1][2 + (t & 1)];
                    mma16816(acc[mt][t], ah[mt], b0, b1);
                    mma16816(acc[mt][t], al[mt], b0, b1);
                }
            #pragma unroll
            for (int pt = 0; pt < WNT / 2; pt++) {
                uint32_t r = bst + (uint32_t)(BN * 40 * 2) +
                             (uint32_t)(((wn * (BN / 2) + pt * 16 + lrow) * 40 + ks * 16 + lcol) * 2);
                ldsm4(bf[pt], r);
            }
            #pragma unroll
            for (int mt = 0; mt < 2; mt++)
                #pragma unroll
                for (int t = 0; t < WNT; t++) {
                    uint32_t b0 = bf[t >> 1][t & 1], b1 = bf[t >> 1][2 + (t & 1)];
                    mma16816(acc[mt][t], ah[mt], b0, b1);
                }
        }
        // ---- store A(kt+1) into the other sA stage (readers were mma(kt-1), sync-separated)
        if (kt + 1 < NCH) storeA(kt + 1, f);
    }
    // ---- epilogue
    int gq = lane >> 2, tg = lane & 3;
    #pragma unroll
    for (int mt = 0; mt < 2; mt++) {
        #pragma unroll
        for (int t = 0; t < WNT; t++) {
            int col = wn * (BN / 2) + t * 8 + tg * 2;
            float u0 = Ub[col], u1 = Ub[col + 1];
            int r0 = row0 + wm * 32 + mt * 16 + gq;
            float v0 = acc[mt][t][0] + u0, v1 = acc[mt][t][1] + u1;
            float v2 = acc[mt][t][2] + u0, v3 = acc[mt][t][3] + u1;
            if (RELU) {
                v0 = fmaxf(v0, 0.f); v1 = fmaxf(v1, 0.f);
                v2 = fmaxf(v2, 0.f); v3 = fmaxf(v3, 0.f);
            }
            if (r0 < M)     *(float2*)&C[(size_t)r0 * BN + col]       = make_float2(v0, v1);
            if (r0 + 8 < M) *(float2*)&C[(size_t)(r0 + 8) * BN + col] = make_float2(v2, v3);
        }
    }
}

// ---------------- mma.sync PQ GEMM: same 3-stage B / 2-stage A pipeline ------
template <int INSEL, int L>
__global__ __launch_bounds__(256, 2) void mma_pq(const float* __restrict__ hin,
                                                 const float* __restrict__ Mb, int M) {
    constexpr int KTOT = 128, NCH = 4, BN = 128, WNT = 8;
    constexpr int SA_STAGE = 2 * 128 * 40;
    constexpr int SB_STAGE = 2 * BN * 40;
    extern __shared__ __align__(16) char dyn[];
    uint16_t* sA = (uint16_t*)dyn;
    uint16_t* sB = (uint16_t*)(dyn + 2 * SA_STAGE * 2);
    const float* H = sel_in<INSEL>(hin);
    int mat = blockIdx.y;
    float* C = mat ? g_Q : g_P;

    int tid = threadIdx.x, lane = tid & 31, wid = tid >> 5;
    int wm = wid & 3, wn = wid >> 2;
    int row0  = blockIdx.x * 128;
    int arow  = tid >> 1, ahalf = (tid & 1) * 16;
    int gr_a  = row0 + arow;
    bool va   = gr_a < M;

    float acc[2][WNT][4];
    #pragma unroll
    for (int mt = 0; mt < 2; mt++)
        #pragma unroll
        for (int t = 0; t < WNT; t++)
            #pragma unroll
            for (int j = 0; j < 4; j++) acc[mt][t][j] = 0.f;

    uint32_t a_base = smem_u32(sA);
    uint32_t b_base = smem_u32(sB);
    int lrow = lane & 15, lcol = (lane >> 4) * 8;

    auto fillB = [&](int c) {
        int k0 = c * 32, st = c % 3;
        uint32_t sbase = b_base + (uint32_t)(st * SB_STAGE * 2);
        #pragma unroll
        for (int i = tid; i < BN * 8; i += 256) {
            int img = i >= BN * 4;
            int j   = img ? i - BN * 4 : i;
            int n   = j >> 2, q = j & 3;
            const unsigned short* g = img ? g_PQlo[L] : g_PQhi[L];
            uint32_t daddr = sbase + (uint32_t)(((img * BN + n) * 40 + q * 8) * 2);
            cp_async16(daddr, g + (size_t)(mat * 128 + n) * KTOT + k0 + q * 8);
        }
        CP_COMMIT();
    };
    auto storeA = [&](int c, const float4* f) {
        uint4 Hv[2], Lv[2];
        conv16(f, 1.0f, Hv, Lv);
        uint16_t* base = sA + (size_t)(c & 1) * SA_STAGE;
        *(uint4*)&base[(size_t)arow * 40 + ahalf]             = Hv[0];
        *(uint4*)&base[(size_t)arow * 40 + ahalf + 8]         = Hv[1];
        *(uint4*)&base[(size_t)(128 + arow) * 40 + ahalf]     = Lv[0];
        *(uint4*)&base[(size_t)(128 + arow) * 40 + ahalf + 8] = Lv[1];
    };

    fillB(0);
    fillB(1);
    float4 f[4];
    {
        const float* bp = H + (size_t)gr_a * 128;
        #pragma unroll
        for (int q = 0; q < 4; q++)
            f[q] = va ? *(const float4*)(bp + ahalf + q * 4)
                      : make_float4(0.f, 0.f, 0.f, 0.f);
    }
    storeA(0, f);

    for (int kt = 0; kt < NCH; kt++) {
        if (kt == NCH - 1) CP_WAIT0(); else CP_WAIT1();
        __syncthreads();
        if (kt + 2 < NCH) fillB(kt + 2);
        if (kt + 1 < NCH) {
            const float* bp = H + (size_t)gr_a * 128 + (kt + 1) * 32;
            #pragma unroll
            for (int q = 0; q < 4; q++)
                f[q] = va ? *(const float4*)(bp + ahalf + q * 4)
                          : make_float4(0.f, 0.f, 0.f, 0.f);
        }
        uint32_t ast = a_base + (uint32_t)((kt & 1) * SA_STAGE * 2);
        uint32_t bst = b_base + (uint32_t)((kt % 3) * SB_STAGE * 2);
        #pragma unroll
        for (int ks = 0; ks < 2; ks++) {
            uint32_t ah[2][4], al[2][4];
            #pragma unroll
            for (int mt = 0; mt < 2; mt++) {
                uint32_t r = ast + (uint32_t)(((wm * 32 + mt * 16 + lrow) * 40 + ks * 16 + lcol) * 2);
                ldsm4(ah[mt], r);
                ldsm4(al[mt], r + 128 * 40 * 2);
            }
            uint32_t bf[WNT / 2][4];
            #pragma unroll
            for (int pt = 0; pt < WNT / 2; pt++) {
                uint32_t r = bst + (uint32_t)(((wn * 64 + pt * 16 + lrow) * 40 + ks * 16 + lcol) * 2);
                ldsm4(bf[pt], r);
            }
            #pragma unroll
            for (int mt = 0; mt < 2; mt++)
                #pragma unroll
                for (int t = 0; t < WNT; t++) {
                    uint32_t b0 = bf[t >> 1][t & 1], b1 = bf[t >> 1][2 + (t & 1)];
                    mma16816(acc[mt][t], ah[mt], b0, b1);
                    mma16816(acc[mt][t], al[mt], b0, b1);
                }
            #pragma unroll
            for (int pt = 0; pt < WNT / 2; pt++) {
                uint32_t r = bst + (uint32_t)(BN * 40 * 2) +
                             (uint32_t)(((wn * 64 + pt * 16 + lrow) * 40 + ks * 16 + lcol) * 2);
                ldsm4(bf[pt], r);
            }
            #pragma unroll
            for (int mt = 0; mt < 2; mt++)
                #pragma unroll
                for (int t = 0; t < WNT; t++) {
                    uint32_t b0 = bf[t >> 1][t & 1], b1 = bf[t >> 1][2 + (t & 1)];
                    mma16816(acc[mt][t], ah[mt], b0, b1);
                }
        }
        if (kt + 1 < NCH) storeA(kt + 1, f);
    }
    int gq = lane >> 2, tg = lane & 3;
    #pragma unroll
    for (int mt = 0; mt < 2; mt++) {
        #pragma unroll
        for (int t = 0; t < WNT; t++) {
            int col = wn * 64 + t * 8 + tg * 2;
            float u0 = mat ? Mb[col] : 0.f;
            float u1 = mat ? Mb[col + 1] : 0.f;
            int r0 = row0 + wm * 32 + mt * 16 + gq;
            if (r0 < M)
                *(float2*)&C[(size_t)r0 * 128 + col] =
                    make_float2(acc[mt][t][0] + u0, acc[mt][t][1] + u1);
            if (r0 + 8 < M)
                *(float2*)&C[(size_t)(r0 + 8) * 128 + col] =
                    make_float2(acc[mt][t][2] + u0, acc[mt][t][3] + u1);
        }
    }
}

// ---------------- CSR aggregation: warp per node, manual 2-way unroll ----------------
__global__ void agg_kernel(int n) {
    int gw   = (blockIdx.x * blockDim.x + threadIdx.x) >> 5;
    int lane = threadIdx.x & 31;
    if (gw >= n) return;
    int s = g_off[gw], e = g_off[gw + 1];
    int c = lane * 4;
    float4 sum = make_float4(0.f, 0.f, 0.f, 0.f);
    float4 mn  = make_float4(1e30f, 1e30f, 1e30f, 1e30f);
    float4 mx  = make_float4(-1e30f, -1e30f, -1e30f, -1e30f);
    int i = s;
    for (; i + 2 <= e; i += 2) {
        int r0 = g_csr[i], r1 = g_csr[i + 1];
        float4 v0 = *(const float4*)&g_P[(size_t)r0 * 128 + c];
        float4 v1 = *(const float4*)&g_P[(size_t)r1 * 128 + c];
        sum.x += v0.x + v1.x; sum.y += v0.y + v1.y;
        sum.z += v0.z + v1.z; sum.w += v0.w + v1.w;
        mn.x = fminf(mn.x, fminf(v0.x, v1.x)); mn.y = fminf(mn.y, fminf(v0.y, v1.y));
        mn.z = fminf(mn.z, fminf(v0.z, v1.z)); mn.w = fminf(mn.w, fminf(v0.w, v1.w));
        mx.x = fmaxf(mx.x, fmaxf(v0.x, v1.x)); mx.y = fmaxf(mx.y, fmaxf(v0.y, v1.y));
        mx.z = fmaxf(mx.z, fmaxf(v0.z, v1.z)); mx.w = fmaxf(mx.w, fmaxf(v0.w, v1.w));
    }
    if (i < e) {
        int r = g_csr[i];
        float4 v = *(const float4*)&g_P[(size_t)r * 128 + c];
        sum.x += v.x; sum.y += v.y; sum.z += v.z; sum.w += v.w;
        mn.x = fminf(mn.x, v.x); mn.y = fminf(mn.y, v.y);
        mn.z = fminf(mn.z, v.z); mn.w = fminf(mn.w, v.w);
        mx.x = fmaxf(mx.x, v.x); mx.y = fmaxf(mx.y, v.y);
        mx.z = fmaxf(mx.z, v.z); mx.w = fmaxf(mx.w, v.w);
    }
    float4 q = *(const float4*)&g_Q[(size_t)gw * 128 + c];
    float4 me, on, ox;
    int d = e - s;
    if (d > 0) {
        float inv = 1.0f / (float)d;
        me.x = sum.x * inv + q.x; me.y = sum.y * inv + q.y;
        me.z = sum.z * inv + q.z; me.w = sum.w * inv + q.w;
        on.x = mn.x + q.x; on.y = mn.y + q.y; on.z = mn.z + q.z; on.w = mn.w + q.w;
        ox.x = mx.x + q.x; ox.y = mx.y + q.y; ox.z = mx.z + q.z; ox.w = mx.w + q.w;
    } else {
        me = make_float4(0.f, 0.f, 0.f, 0.f);
        on = me; ox = me;
    }
    *(float4*)&g_agg[(size_t)gw * 384 + c]       = me;
    *(float4*)&g_agg[(size_t)gw * 384 + 128 + c] = on;
    *(float4*)&g_agg[(size_t)gw * 384 + 256 + c] = ox;
}

// ---------------- host launcher ----------------
extern "C" void kernel_launch(void* const* d_in, const int* in_sizes, int n_in,
                              void* d_out, int out_size) {
    const float* x   = (const float*)d_in[0];
    const void*  src = d_in[1];
    const void*  dst = d_in[2];
    const float* M0w = (const float*)d_in[3];
    const float* M0b = (const float*)d_in[4];
    const float* U0w = (const float*)d_in[5];
    const float* U0b = (const float*)d_in[6];
    const float* M1w = (const float*)d_in[7];
    const float* M1b = (const float*)d_in[8];
    const float* U1w = (const float*)d_in[9];
    const float* U1b = (const float*)d_in[10];
    const float* M2w = (const float*)d_in[11];
    const float* M2b = (const float*)d_in[12];
    const float* U2w = (const float*)d_in[13];
    const float* U2b = (const float*)d_in[14];

    int n = in_sizes[0] / 128;
    int e = in_sizes[1];
    if (n > NN) n = NN;
    if (e > NE) e = NE;

    static cudaStream_t s1 = nullptr, s2 = nullptr;
    static cudaEvent_t evStart1 = nullptr, evStart2 = nullptr, evCSR = nullptr, evPre = nullptr;
    if (s1 == nullptr) {
        cudaStreamCreateWithFlags(&s1, cudaStreamNonBlocking);
        cudaStreamCreateWithFlags(&s2, cudaStreamNonBlocking);
        cudaEventCreateWithFlags(&evStart1, cudaEventDisableTiming);
        cudaEventCreateWithFlags(&evStart2, cudaEventDisableTiming);
        cudaEventCreateWithFlags(&evCSR, cudaEventDisableTiming);
        cudaEventCreateWithFlags(&evPre, cudaEventDisableTiming);
    }

    // smem: sA 2 stages (40960B) + sB 3 stages
    const int UPD_SMEM_H = 40960 + 3 * 20480;  // 102400 (BN=128)
    const int UPD_SMEM_L = 40960 + 3 * 10240;  // 71680  (BN=64)
    const int PQ_SMEM    = 40960 + 3 * 20480;  // 102400
    cudaFuncSetAttribute(mma_update<0, 1, 128, true, 0>,
                         cudaFuncAttributeMaxDynamicSharedMemorySize, UPD_SMEM_H);
    cudaFuncSetAttribute(mma_update<1, 2, 128, true, 1>,
                         cudaFuncAttributeMaxDynamicSharedMemorySize, UPD_SMEM_H);
    cudaFuncSetAttribute(mma_update<2, 0, 64, false, 2>,
                         cudaFuncAttributeMaxDynamicSharedMemorySize, UPD_SMEM_L);
    cudaFuncSetAttribute(mma_pq<0, 0>,
                         cudaFuncAttributeMaxDynamicSharedMemorySize, PQ_SMEM);
    cudaFuncSetAttribute(mma_pq<1, 1>,
                         cudaFuncAttributeMaxDynamicSharedMemorySize, PQ_SMEM);
    cudaFuncSetAttribute(mma_pq<2, 2>,
                         cudaFuncAttributeMaxDynamicSharedMemorySize, PQ_SMEM);

    int gE = (e + 255) / 256;
    int gN = (n + 255) / 256;
    int gM = (n + 127) / 128;
    int gA = (n * 32 + 255) / 256;
    int nb = (n + 1023) / 1024;

    // fork: s1 = CSR build, s2 = remaining prepacks; main starts layer-0 PQ
    cudaEventRecord(evStart1, 0);
    cudaStreamWaitEvent(s1, evStart1, 0);
    cudaEventRecord(evStart2, 0);
    cudaStreamWaitEvent(s2, evStart2, 0);

    // s1: CSR build + node scalars
    detect_kernel<<<1, 256, 0, s1>>>(dst, e, n);
    zero_deg<<<gN, 256, 0, s1>>>(n);
    hist_kernel<<<gE, 256, 0, s1>>>(dst, e);
    scan_p1<<<nb, 256, 0, s1>>>(n);
    scan_p2<<<1, 64, 0, s1>>>(nb, n);
    scan_p3<<<nb, 256, 0, s1>>>(n);
    scatter_kernel<<<gE, 256, 0, s1>>>(src, dst, e);
    cudaEventRecord(evCSR, s1);

    // s2: all update prepacks + later-layer PQ prepacks
    prepack_upd2<0><<<(1280 * 128 + 255) / 256, 256, 0, s2>>>(U0w, 128);
    prepack_upd2<1><<<(1280 * 128 + 255) / 256, 256, 0, s2>>>(U1w, 128);
    prepack_upd2<2><<<(1280 * 64 + 255) / 256, 256, 0, s2>>>(U2w, 64);
    prepack_pq2<1><<<128, 256, 0, s2>>>(M1w);
    prepack_pq2<2><<<128, 256, 0, s2>>>(M2w);
    cudaEventRecord(evPre, s2);

    // main: layer 0 PQ (needs only its own prepack)
    prepack_pq2<0><<<128, 256>>>(M0w);
    mma_pq<0, 0><<<dim3(gM, 2), 256, PQ_SMEM>>>(x, M0b, n);
    cudaStreamWaitEvent(0, evCSR, 0);   // agg needs CSR
    agg_kernel<<<gA, 256>>>(n);
    cudaStreamWaitEvent(0, evPre, 0);   // update needs its prepack
    mma_update<0, 1, 128, true, 0><<<gM, 256, UPD_SMEM_H>>>(x, U0b, nullptr, n);

    // layer 1
    mma_pq<1, 1><<<dim3(gM, 2), 256, PQ_SMEM>>>(nullptr, M1b, n);
    agg_kernel<<<gA, 256>>>(n);
    mma_update<1, 2, 128, true, 1><<<gM, 256, UPD_SMEM_H>>>(nullptr, U1b, nullptr, n);

    // layer 2 (N=64, no relu)
    mma_pq<2, 2><<<dim3(gM, 2), 256, PQ_SMEM>>>(nullptr, M2b, n);
    agg_kernel<<<gA, 256>>>(n);
    mma_update<2, 0, 64, false, 2><<<gM, 256, UPD_SMEM_L>>>(nullptr, U2b, (float*)d_out, n);
}